// round 10
// baseline (speedup 1.0000x reference)
#include <cuda_runtime.h>
#include <cuda_bf16.h>
#include <cuda_fp16.h>
#include <cstdint>

#define NN     50000
#define IN_C   256
#define HID_C  128
#define OUT_C  64
#define E_MAX  800000
#define NB     ((NN + 255) / 256)   // 196 scan blocks

// ---------------- scratch ----------------
__device__ __align__(16) float g_dinv[NN];
__device__ __align__(16) int   g_degi[NN];          // zeroed at END of each call
__device__ __align__(16) int   g_row [NN + 1];
__device__ __align__(16) int   g_cur [NN];
__device__ __align__(16) unsigned long long g_desc[NB];  // zeroed at END of each call
__device__ __align__(16) int   g_csr [E_MAX];
__device__ __align__(16) __half g_h2  [NN * HID_C];
__device__ __align__(16) __half g_agg1[NN * HID_C];
__device__ __align__(16) __half g_z2  [NN * OUT_C];
__device__ __align__(16) __nv_bfloat16 g_xhi[NN * IN_C];   // x split hi
__device__ __align__(16) __nv_bfloat16 g_xlo[NN * IN_C];   // x split lo
__device__ __align__(16) __nv_bfloat16 g_w1hi[HID_C * IN_C];
__device__ __align__(16) __nv_bfloat16 g_w1lo[HID_C * IN_C];
__device__ __align__(16) __nv_bfloat16 g_w2hi[OUT_C * HID_C];
__device__ __align__(16) __nv_bfloat16 g_w2lo[OUT_C * HID_C];

__device__ __forceinline__ uint32_t smem_u32(const void* p) {
    uint32_t a;
    asm("{ .reg .u64 t; cvta.to.shared.u64 t, %1; cvt.u32.u64 %0, t; }" : "=r"(a) : "l"(p));
    return a;
}
__device__ __forceinline__ void cp16(uint32_t saddr, const void* g) {
    asm volatile("cp.async.cg.shared.global [%0], [%1], 16;" :: "r"(saddr), "l"(g));
}

// ---------------- prep: deg histogram + W conversion + x hi/lo split ---------
__global__ void prep_count_kernel(const int* __restrict__ dst, int E,
                                  const float* __restrict__ x,
                                  const float* __restrict__ W1, const float* __restrict__ W2,
                                  int* __restrict__ degi,
                                  __nv_bfloat16* __restrict__ xhi, __nv_bfloat16* __restrict__ xlo,
                                  __nv_bfloat16* __restrict__ w1hi, __nv_bfloat16* __restrict__ w1lo,
                                  __nv_bfloat16* __restrict__ w2hi, __nv_bfloat16* __restrict__ w2lo) {
    const int W1N = IN_C * HID_C;
    const int W2N = HID_C * OUT_C;
    const int XQ  = NN * IN_C / 4;
    int idx = blockIdx.x * blockDim.x + threadIdx.x;
    if (idx < E) {
        atomicAdd(&degi[dst[idx]], 1);
    } else if (idx < E + W1N) {
        int i = idx - E;
        int n = i / IN_C, k = i % IN_C;
        float v = W1[(long long)k * HID_C + n];
        __nv_bfloat16 hi = __float2bfloat16_rn(v);
        w1hi[i] = hi;
        w1lo[i] = __float2bfloat16_rn(v - __bfloat162float(hi));
    } else if (idx < E + W1N + W2N) {
        int i = idx - E - W1N;
        int n = i / HID_C, k = i % HID_C;
        float v = W2[(long long)k * OUT_C + n];
        __nv_bfloat16 hi = __float2bfloat16_rn(v);
        w2hi[i] = hi;
        w2lo[i] = __float2bfloat16_rn(v - __bfloat162float(hi));
    } else if (idx < E + W1N + W2N + XQ) {
        int i = idx - E - W1N - W2N;     // one float4 per thread
        float4 v = reinterpret_cast<const float4*>(x)[i];
        __nv_bfloat162 h01 = __floats2bfloat162_rn(v.x, v.y);
        __nv_bfloat162 h23 = __floats2bfloat162_rn(v.z, v.w);
        float lx = v.x - __bfloat162float(__low2bfloat16(h01));
        float ly = v.y - __bfloat162float(__high2bfloat16(h01));
        float lz = v.z - __bfloat162float(__low2bfloat16(h23));
        float lw = v.w - __bfloat162float(__high2bfloat16(h23));
        __nv_bfloat162 l01 = __floats2bfloat162_rn(lx, ly);
        __nv_bfloat162 l23 = __floats2bfloat162_rn(lz, lw);
        reinterpret_cast<uint2*>(xhi)[i] =
            make_uint2(*reinterpret_cast<uint32_t*>(&h01), *reinterpret_cast<uint32_t*>(&h23));
        reinterpret_cast<uint2*>(xlo)[i] =
            make_uint2(*reinterpret_cast<uint32_t*>(&l01), *reinterpret_cast<uint32_t*>(&l23));
    }
}

// ---------------- single-pass scan (decoupled lookback) + dinv ---------------
__global__ void scan_kernel(const int* __restrict__ deg, unsigned long long* __restrict__ desc,
                            int* __restrict__ row, int* __restrict__ cur,
                            float* __restrict__ dinv, int n) {
    __shared__ int s[256];
    __shared__ int s_carry;
    const int bid = blockIdx.x;
    const int t   = threadIdx.x;
    const int i   = bid * 256 + t;
    int v = (i < n) ? deg[i] : 0;
    s[t] = v;
    __syncthreads();
    #pragma unroll
    for (int off = 1; off < 256; off <<= 1) {
        int u = (t >= off) ? s[t - off] : 0;
        __syncthreads();
        s[t] += u;
        __syncthreads();
    }
    int total = s[255];
    if (t == 0) {
        unsigned long long d = ((unsigned long long)(bid == 0 ? 2u : 1u) << 32)
                             | (unsigned int)total;
        atomicExch(&desc[bid], d);
        if (bid == 0) s_carry = 0;
    }
    if (bid > 0 && t < 32) {
        int carry = 0;
        int j = bid - 1;
        while (true) {
            int jj = j - t;
            unsigned long long d = 0ULL;
            if (jj >= 0) d = *((volatile unsigned long long*)&desc[jj]);
            int st  = (int)(d >> 32);
            int val = (int)(d & 0xffffffffu);
            unsigned ready = __ballot_sync(0xffffffffu, (jj < 0) || st >= 1);
            if (ready != 0xffffffffu) continue;
            unsigned pmask = __ballot_sync(0xffffffffu, (jj >= 0) && st == 2);
            if (pmask) {
                int lp = __ffs(pmask) - 1;
                int contrib = (jj >= 0 && t <= lp) ? val : 0;
                #pragma unroll
                for (int o = 16; o > 0; o >>= 1)
                    contrib += __shfl_down_sync(0xffffffffu, contrib, o);
                carry += __shfl_sync(0xffffffffu, contrib, 0);
                break;
            } else {
                int contrib = (jj >= 0) ? val : 0;
                #pragma unroll
                for (int o = 16; o > 0; o >>= 1)
                    contrib += __shfl_down_sync(0xffffffffu, contrib, o);
                carry += __shfl_sync(0xffffffffu, contrib, 0);
                j -= 32;
                if (j < 0) break;
            }
        }
        if (t == 0) {
            atomicExch(&desc[bid], (2ULL << 32) | (unsigned int)(carry + total));
            s_carry = carry;
        }
    }
    __syncthreads();
    int carry = s_carry;
    if (i < n) {
        int excl = carry + s[t] - v;
        row[i] = excl;
        cur[i] = excl;
        dinv[i] = rsqrtf((float)v + 1.0f);
        if (i == n - 1) row[n] = excl + v;
    }
}

__global__ void slot_scatter_kernel(const int* __restrict__ src, const int* __restrict__ dst,
                                    int* __restrict__ cur, int* __restrict__ csr, int E) {
    int e = blockIdx.x * blockDim.x + threadIdx.x;
    if (e < E) {
        int pos = atomicAdd(&cur[dst[e]], 1);
        csr[pos] = src[e];
    }
}

// ---------------- mma.sync helper -------------------------------------------
__device__ __forceinline__ void mma16816(float c[4], const uint32_t a[4], const uint32_t b[2]) {
    asm volatile(
        "mma.sync.aligned.m16n8k16.row.col.f32.bf16.bf16.f32 "
        "{%0,%1,%2,%3}, {%4,%5,%6,%7}, {%8,%9}, {%0,%1,%2,%3};"
        : "+f"(c[0]), "+f"(c[1]), "+f"(c[2]), "+f"(c[3])
        : "r"(a[0]), "r"(a[1]), "r"(a[2]), "r"(a[3]), "r"(b[0]), "r"(b[1]));
}

// ---------------- GEMM1: pure-copy, cp.async double-buffered -----------------
// C = fp16( dinv[r] * (x @ W1) ), x pre-split to bf16 hi/lo.
// BM=128, BN=128, BK=32, K=256 (8 chunks). LD=40 (conflict-free padding).
__global__ void __launch_bounds__(256, 2)
mma_gemm1(const __nv_bfloat16* __restrict__ Ahi, const __nv_bfloat16* __restrict__ Alo,
          const __nv_bfloat16* __restrict__ Whi, const __nv_bfloat16* __restrict__ Wlo,
          __half* __restrict__ C, const float* __restrict__ dinv, int M) {
    const int BN = 128, BK = 32, K = 256, LD = 40;
    const int NCH = K / BK;                 // 8
    const int TILE = 128 * LD * 2;          // 10240 B per tile
    const int STAGE = 4 * TILE;             // A_hi A_lo B_hi B_lo = 40960 B

    extern __shared__ __align__(16) char smem[];
    const uint32_t sbase0 = smem_u32(smem);

    const int tid  = threadIdx.x;
    const int wid  = tid >> 5;
    const int lane = tid & 31;
    const int g    = lane >> 2;
    const int t    = lane & 3;
    const int wm   = wid & 3;               // 4 m-groups of 32 rows
    const int wn   = wid >> 2;              // 2 n-groups of 64 cols
    const int row0 = blockIdx.x * 128;

    float acc[2][8][4];
    #pragma unroll
    for (int mt = 0; mt < 2; mt++)
        #pragma unroll
        for (int nt = 0; nt < 8; nt++)
            #pragma unroll
            for (int q = 0; q < 4; q++) acc[mt][nt][q] = 0.0f;

    // copy chunk kc into stage st
    auto copy_chunk = [&](int kc, int st) {
        uint32_t sb = sbase0 + st * STAGE;
        #pragma unroll
        for (int i = 0; i < 4; i++) {            // A: 1024 x 16B
            int cid = tid + i * 256;
            int half = cid >> 9;
            int r    = (cid >> 2) & 127;
            int k8   = (cid & 3) * 8;
            int gr   = row0 + r;
            if (gr < M) {
                const __nv_bfloat16* src = (half ? Alo : Ahi) + (long long)gr * K + kc + k8;
                cp16(sb + half * TILE + (r * LD + k8) * 2, src);
            }
        }
        #pragma unroll
        for (int i = 0; i < 4; i++) {            // B: 1024 x 16B
            int cid = tid + i * 256;
            int half = cid >> 9;
            int n    = (cid >> 2) & 127;
            int k8   = (cid & 3) * 8;
            const __nv_bfloat16* src = (half ? Wlo : Whi) + (long long)n * K + kc + k8;
            cp16(sb + 2 * TILE + half * TILE + (n * LD + k8) * 2, src);
        }
        asm volatile("cp.async.commit_group;");
    };

    copy_chunk(0, 0);
    for (int c = 0; c < NCH; c++) {
        if (c + 1 < NCH) {
            copy_chunk((c + 1) * BK, (c + 1) & 1);
            asm volatile("cp.async.wait_group 1;");
        } else {
            asm volatile("cp.async.wait_group 0;");
        }
        __syncthreads();

        const char* sb = smem + (c & 1) * STAGE;
        const __nv_bfloat16* as_hi = reinterpret_cast<const __nv_bfloat16*>(sb);
        const __nv_bfloat16* as_lo = reinterpret_cast<const __nv_bfloat16*>(sb + TILE);
        const __nv_bfloat16* bs_hi = reinterpret_cast<const __nv_bfloat16*>(sb + 2 * TILE);
        const __nv_bfloat16* bs_lo = reinterpret_cast<const __nv_bfloat16*>(sb + 3 * TILE);

        #pragma unroll
        for (int kk = 0; kk < BK; kk += 16) {
            uint32_t ah[2][4], al[2][4];
            #pragma unroll
            for (int mt = 0; mt < 2; mt++) {
                int ar = wm * 32 + mt * 16;
                int o00 = (ar + g) * LD + kk + 2 * t;
                int o10 = (ar + 8 + g) * LD + kk + 2 * t;
                ah[mt][0] = *reinterpret_cast<const uint32_t*>(as_hi + o00);
                ah[mt][1] = *reinterpret_cast<const uint32_t*>(as_hi + o10);
                ah[mt][2] = *reinterpret_cast<const uint32_t*>(as_hi + o00 + 8);
                ah[mt][3] = *reinterpret_cast<const uint32_t*>(as_hi + o10 + 8);
                al[mt][0] = *reinterpret_cast<const uint32_t*>(as_lo + o00);
                al[mt][1] = *reinterpret_cast<const uint32_t*>(as_lo + o10);
                al[mt][2] = *reinterpret_cast<const uint32_t*>(as_lo + o00 + 8);
                al[mt][3] = *reinterpret_cast<const uint32_t*>(as_lo + o10 + 8);
            }
            #pragma unroll
            for (int nt = 0; nt < 8; nt++) {
                int bn = wn * 64 + nt * 8 + g;
                int ob = bn * LD + kk + 2 * t;
                uint32_t bh[2], bl[2];
                bh[0] = *reinterpret_cast<const uint32_t*>(bs_hi + ob);
                bh[1] = *reinterpret_cast<const uint32_t*>(bs_hi + ob + 8);
                bl[0] = *reinterpret_cast<const uint32_t*>(bs_lo + ob);
                bl[1] = *reinterpret_cast<const uint32_t*>(bs_lo + ob + 8);
                #pragma unroll
                for (int mt = 0; mt < 2; mt++) {
                    mma16816(acc[mt][nt], ah[mt], bh);
                    mma16816(acc[mt][nt], ah[mt], bl);
                    mma16816(acc[mt][nt], al[mt], bh);
                }
            }
        }
        __syncthreads();
    }

    #pragma unroll
    for (int mt = 0; mt < 2; mt++) {
        int r0 = row0 + wm * 32 + mt * 16 + g;
        int r1 = r0 + 8;
        float s0 = (r0 < M) ? dinv[r0] : 0.0f;
        float s1 = (r1 < M) ? dinv[r1] : 0.0f;
        #pragma unroll
        for (int nt = 0; nt < 8; nt++) {
            int cc = wn * 64 + nt * 8 + 2 * t;
            if (r0 < M)
                *reinterpret_cast<__half2*>(C + (long long)r0 * BN + cc) =
                    __floats2half2_rn(s0 * acc[mt][nt][0], s0 * acc[mt][nt][1]);
            if (r1 < M)
                *reinterpret_cast<__half2*>(C + (long long)r1 * BN + cc) =
                    __floats2half2_rn(s1 * acc[mt][nt][2], s1 * acc[mt][nt][3]);
        }
    }
}

// ---------------- GEMM2 (R9 structure): A fp16 + relu transform --------------
__global__ void __launch_bounds__(256, 2)
mma_gemm2(const __half* __restrict__ Ah2,
          const __nv_bfloat16* __restrict__ Whi, const __nv_bfloat16* __restrict__ Wlo,
          __half* __restrict__ C,
          const float* __restrict__ dinv, const float* __restrict__ bias, int M) {
    const int BN = OUT_C, KTOT = HID_C;
    const int BM = 128, BK = 64, LD = 72;
    const int NW = BN / 2;      // 32
    const int NT = NW / 8;      // 4
    const int A_HI = 0;
    const int A_LO = A_HI + BM * LD * 2;
    const int B_HI = A_LO + BM * LD * 2;
    const int B_LO = B_HI + BN * LD * 2;

    extern __shared__ __align__(16) char smem[];
    __nv_bfloat16* as_hi = reinterpret_cast<__nv_bfloat16*>(smem + A_HI);
    __nv_bfloat16* as_lo = reinterpret_cast<__nv_bfloat16*>(smem + A_LO);
    __nv_bfloat16* bs_hi = reinterpret_cast<__nv_bfloat16*>(smem + B_HI);
    __nv_bfloat16* bs_lo = reinterpret_cast<__nv_bfloat16*>(smem + B_LO);

    const int tid  = threadIdx.x;
    const int wid  = tid >> 5;
    const int lane = tid & 31;
    const int g    = lane >> 2;
    const int t    = lane & 3;
    const int wm   = wid & 3;
    const int wn   = wid >> 2;
    const int row0 = blockIdx.x * BM;

    float acc[2][NT][4];
    #pragma unroll
    for (int mt = 0; mt < 2; mt++)
        #pragma unroll
        for (int nt = 0; nt < NT; nt++)
            #pragma unroll
            for (int q = 0; q < 4; q++) acc[mt][nt][q] = 0.0f;

    for (int kc = 0; kc < KTOT; kc += BK) {
        #pragma unroll
        for (int it = 0; it < (BM * BK / 4) / 256; it++) {
            int idx = tid + it * 256;
            int row = idx >> 4;
            int k4  = (idx & 15) * 4;
            int gr  = row0 + row;
            float4 v = make_float4(0.f, 0.f, 0.f, 0.f);
            if (gr < M) {
                uint2 u = *reinterpret_cast<const uint2*>(Ah2 + (long long)gr * KTOT + kc + k4);
                float2 f0 = __half22float2(*reinterpret_cast<__half2*>(&u.x));
                float2 f1 = __half22float2(*reinterpret_cast<__half2*>(&u.y));
                float di = dinv[gr];
                float4 bb = *reinterpret_cast<const float4*>(bias + kc + k4);
                v.x = fmaxf(fmaf(di, f0.x, bb.x), 0.f);
                v.y = fmaxf(fmaf(di, f0.y, bb.y), 0.f);
                v.z = fmaxf(fmaf(di, f1.x, bb.z), 0.f);
                v.w = fmaxf(fmaf(di, f1.y, bb.w), 0.f);
            }
            __nv_bfloat162 h01 = __floats2bfloat162_rn(v.x, v.y);
            __nv_bfloat162 h23 = __floats2bfloat162_rn(v.z, v.w);
            float lx = v.x - __bfloat162float(__low2bfloat16(h01));
            float ly = v.y - __bfloat162float(__high2bfloat16(h01));
            float lz = v.z - __bfloat162float(__low2bfloat16(h23));
            float lw = v.w - __bfloat162float(__high2bfloat16(h23));
            __nv_bfloat162 l01 = __floats2bfloat162_rn(lx, ly);
            __nv_bfloat162 l23 = __floats2bfloat162_rn(lz, lw);
            int off = row * LD + k4;
            *reinterpret_cast<uint2*>(as_hi + off) =
                make_uint2(*reinterpret_cast<uint32_t*>(&h01), *reinterpret_cast<uint32_t*>(&h23));
            *reinterpret_cast<uint2*>(as_lo + off) =
                make_uint2(*reinterpret_cast<uint32_t*>(&l01), *reinterpret_cast<uint32_t*>(&l23));
        }
        #pragma unroll
        for (int it = 0; it < (BN * BK / 4) / 256; it++) {
            int idx = tid + it * 256;
            int n  = idx >> 4;
            int k4 = (idx & 15) * 4;
            uint2 wh = *reinterpret_cast<const uint2*>(Whi + (long long)n * KTOT + kc + k4);
            uint2 wl = *reinterpret_cast<const uint2*>(Wlo + (long long)n * KTOT + kc + k4);
            int off = n * LD + k4;
            *reinterpret_cast<uint2*>(bs_hi + off) = wh;
            *reinterpret_cast<uint2*>(bs_lo + off) = wl;
        }
        __syncthreads();

        #pragma unroll
        for (int kk = 0; kk < BK; kk += 16) {
            uint32_t ah[2][4], al[2][4];
            #pragma unroll
            for (int mt = 0; mt < 2; mt++) {
                int ar = wm * 32 + mt * 16;
                int o00 = (ar + g) * LD + kk + 2 * t;
                int o10 = (ar + 8 + g) * LD + kk + 2 * t;
                ah[mt][0] = *reinterpret_cast<const uint32_t*>(as_hi + o00);
                ah[mt][1] = *reinterpret_cast<const uint32_t*>(as_hi + o10);
                ah[mt][2] = *reinterpret_cast<const uint32_t*>(as_hi + o00 + 8);
                ah[mt][3] = *reinterpret_cast<const uint32_t*>(as_hi + o10 + 8);
                al[mt][0] = *reinterpret_cast<const uint32_t*>(as_lo + o00);
                al[mt][1] = *reinterpret_cast<const uint32_t*>(as_lo + o10);
                al[mt][2] = *reinterpret_cast<const uint32_t*>(as_lo + o00 + 8);
                al[mt][3] = *reinterpret_cast<const uint32_t*>(as_lo + o10 + 8);
            }
            #pragma unroll
            for (int nt = 0; nt < NT; nt++) {
                int bn = wn * NW + nt * 8 + g;
                int ob = bn * LD + kk + 2 * t;
                uint32_t bh[2], bl[2];
                bh[0] = *reinterpret_cast<const uint32_t*>(bs_hi + ob);
                bh[1] = *reinterpret_cast<const uint32_t*>(bs_hi + ob + 8);
                bl[0] = *reinterpret_cast<const uint32_t*>(bs_lo + ob);
                bl[1] = *reinterpret_cast<const uint32_t*>(bs_lo + ob + 8);
                #pragma unroll
                for (int mt = 0; mt < 2; mt++) {
                    mma16816(acc[mt][nt], ah[mt], bh);
                    mma16816(acc[mt][nt], ah[mt], bl);
                    mma16816(acc[mt][nt], al[mt], bh);
                }
            }
        }
        __syncthreads();
    }

    #pragma unroll
    for (int mt = 0; mt < 2; mt++) {
        int r0 = row0 + wm * 32 + mt * 16 + g;
        int r1 = r0 + 8;
        float s0 = (r0 < M) ? dinv[r0] : 0.0f;
        float s1 = (r1 < M) ? dinv[r1] : 0.0f;
        #pragma unroll
        for (int nt = 0; nt < NT; nt++) {
            int cc = wn * NW + nt * 8 + 2 * t;
            if (r0 < M)
                *reinterpret_cast<__half2*>(C + (long long)r0 * BN + cc) =
                    __floats2half2_rn(s0 * acc[mt][nt][0], s0 * acc[mt][nt][1]);
            if (r1 < M)
                *reinterpret_cast<__half2*>(C + (long long)r1 * BN + cc) =
                    __floats2half2_rn(s1 * acc[mt][nt][2], s1 * acc[mt][nt][3]);
        }
    }
}

// ---------------- pull layer 1 (fp16): agg1[d] = h2[d] + sum h2[src] ---------
__global__ void pull128_kernel(const __half* __restrict__ h2,
                               const int* __restrict__ row, const int* __restrict__ csr,
                               __half* __restrict__ agg, int n) {
    int gw = (blockIdx.x * blockDim.x + threadIdx.x) >> 5;
    int lane = threadIdx.x & 31;
    if (gw >= n) return;
    long long base = (long long)gw * HID_C + lane * 4;
    uint2 su = *reinterpret_cast<const uint2*>(h2 + base);
    float2 sf0 = __half22float2(*reinterpret_cast<__half2*>(&su.x));
    float2 sf1 = __half22float2(*reinterpret_cast<__half2*>(&su.y));
    float4 a = make_float4(sf0.x, sf0.y, sf1.x, sf1.y);
    int beg = row[gw], end = row[gw + 1];
    int j = beg;
    for (; j + 3 < end; j += 4) {
        int s0 = csr[j], s1 = csr[j + 1], s2 = csr[j + 2], s3 = csr[j + 3];
        uint2 u0 = *reinterpret_cast<const uint2*>(h2 + (long long)s0 * HID_C + lane * 4);
        uint2 u1 = *reinterpret_cast<const uint2*>(h2 + (long long)s1 * HID_C + lane * 4);
        uint2 u2 = *reinterpret_cast<const uint2*>(h2 + (long long)s2 * HID_C + lane * 4);
        uint2 u3 = *reinterpret_cast<const uint2*>(h2 + (long long)s3 * HID_C + lane * 4);
        float2 f;
        f = __half22float2(*reinterpret_cast<__half2*>(&u0.x)); a.x += f.x; a.y += f.y;
        f = __half22float2(*reinterpret_cast<__half2*>(&u0.y)); a.z += f.x; a.w += f.y;
        f = __half22float2(*reinterpret_cast<__half2*>(&u1.x)); a.x += f.x; a.y += f.y;
        f = __half22float2(*reinterpret_cast<__half2*>(&u1.y)); a.z += f.x; a.w += f.y;
        f = __half22float2(*reinterpret_cast<__half2*>(&u2.x)); a.x += f.x; a.y += f.y;
        f = __half22float2(*reinterpret_cast<__half2*>(&u2.y)); a.z += f.x; a.w += f.y;
        f = __half22float2(*reinterpret_cast<__half2*>(&u3.x)); a.x += f.x; a.y += f.y;
        f = __half22float2(*reinterpret_cast<__half2*>(&u3.y)); a.z += f.x; a.w += f.y;
    }
    for (; j < end; j++) {
        int s0 = csr[j];
        uint2 u0 = *reinterpret_cast<const uint2*>(h2 + (long long)s0 * HID_C + lane * 4);
        float2 f;
        f = __half22float2(*reinterpret_cast<__half2*>(&u0.x)); a.x += f.x; a.y += f.y;
        f = __half22float2(*reinterpret_cast<__half2*>(&u0.y)); a.z += f.x; a.w += f.y;
    }
    __half2 o0 = __floats2half2_rn(a.x, a.y);
    __half2 o1 = __floats2half2_rn(a.z, a.w);
    *reinterpret_cast<uint2*>(agg + base) =
        make_uint2(*reinterpret_cast<uint32_t*>(&o0), *reinterpret_cast<uint32_t*>(&o1));
}

// ---------------- pull layer 2 (fp16) + degi/desc reset tail -----------------
__global__ void pull64_kernel(const __half* __restrict__ z2,
                              const int* __restrict__ row, const int* __restrict__ csr,
                              const float* __restrict__ dinv, const float* __restrict__ b2,
                              float* __restrict__ out, int n,
                              int pull_blocks, int* __restrict__ degi,
                              unsigned long long* __restrict__ desc) {
    if ((int)blockIdx.x >= pull_blocks) {
        int base = ((int)blockIdx.x - pull_blocks) * 2048 + threadIdx.x * 8;
        #pragma unroll
        for (int k = 0; k < 8; k++) {
            int i = base + k;
            if (i < NN) degi[i] = 0;
            else if (i - NN < NB) desc[i - NN] = 0ULL;
        }
        return;
    }
    int gw = (blockIdx.x * blockDim.x + threadIdx.x) >> 5;
    int lane = threadIdx.x & 31;
    if (gw >= n) return;
    long long base = (long long)gw * OUT_C + lane * 2;
    float2 a = __half22float2(*reinterpret_cast<const __half2*>(z2 + base));
    int beg = row[gw], end = row[gw + 1];
    int j = beg;
    for (; j + 3 < end; j += 4) {
        int s0 = csr[j], s1 = csr[j + 1], s2 = csr[j + 2], s3 = csr[j + 3];
        float2 f0 = __half22float2(*reinterpret_cast<const __half2*>(z2 + (long long)s0 * OUT_C + lane * 2));
        float2 f1 = __half22float2(*reinterpret_cast<const __half2*>(z2 + (long long)s1 * OUT_C + lane * 2));
        float2 f2 = __half22float2(*reinterpret_cast<const __half2*>(z2 + (long long)s2 * OUT_C + lane * 2));
        float2 f3 = __half22float2(*reinterpret_cast<const __half2*>(z2 + (long long)s3 * OUT_C + lane * 2));
        a.x += (f0.x + f1.x) + (f2.x + f3.x);
        a.y += (f0.y + f1.y) + (f2.y + f3.y);
    }
    for (; j < end; j++) {
        int s0 = csr[j];
        float2 f0 = __half22float2(*reinterpret_cast<const __half2*>(z2 + (long long)s0 * OUT_C + lane * 2));
        a.x += f0.x; a.y += f0.y;
    }
    float di = dinv[gw];
    float2 bb = *reinterpret_cast<const float2*>(b2 + lane * 2);
    *reinterpret_cast<float2*>(out + base) =
        make_float2(fmaf(di, a.x, bb.x), fmaf(di, a.y, bb.y));
}

// ---------------- launch ----------------
extern "C" void kernel_launch(void* const* d_in, const int* in_sizes, int n_in,
                              void* d_out, int out_size) {
    const float* x  = (const float*)d_in[0];
    const int*   ei = (const int*)  d_in[1];
    const float* W1 = (const float*)d_in[2];
    const float* b1 = (const float*)d_in[3];
    const float* W2 = (const float*)d_in[4];
    const float* b2 = (const float*)d_in[5];
    float* out = (float*)d_out;

    const int E = in_sizes[1] / 2;
    const int* src = ei;
    const int* dst = ei + E;

    float *dinv;
    int *degi, *row, *cur, *csr;
    unsigned long long* desc;
    __half *h2, *agg1, *z2;
    __nv_bfloat16 *xhi, *xlo, *w1hi, *w1lo, *w2hi, *w2lo;
    cudaGetSymbolAddress((void**)&dinv, g_dinv);
    cudaGetSymbolAddress((void**)&degi, g_degi);
    cudaGetSymbolAddress((void**)&row,  g_row);
    cudaGetSymbolAddress((void**)&cur,  g_cur);
    cudaGetSymbolAddress((void**)&desc, g_desc);
    cudaGetSymbolAddress((void**)&csr,  g_csr);
    cudaGetSymbolAddress((void**)&h2,   g_h2);
    cudaGetSymbolAddress((void**)&agg1, g_agg1);
    cudaGetSymbolAddress((void**)&z2,   g_z2);
    cudaGetSymbolAddress((void**)&xhi,  g_xhi);
    cudaGetSymbolAddress((void**)&xlo,  g_xlo);
    cudaGetSymbolAddress((void**)&w1hi, g_w1hi);
    cudaGetSymbolAddress((void**)&w1lo, g_w1lo);
    cudaGetSymbolAddress((void**)&w2hi, g_w2hi);
    cudaGetSymbolAddress((void**)&w2lo, g_w2lo);

    const int SMEM1 = 2 * 4 * 128 * 40 * 2;                  // 81920 B (2 stages)
    const int LD2 = 72;
    const int SMEM2 = 2 * 128 * LD2 * 2 + 2 * 64 * LD2 * 2;  // 55296 B
    cudaFuncSetAttribute(mma_gemm1, cudaFuncAttributeMaxDynamicSharedMemorySize, SMEM1);
    cudaFuncSetAttribute(mma_gemm2, cudaFuncAttributeMaxDynamicSharedMemorySize, SMEM2);

    // 1) prep: degree histogram + W conversion + x hi/lo split
    {
        int total = E + IN_C * HID_C + HID_C * OUT_C + NN * IN_C / 4;
        prep_count_kernel<<<(total + 255) / 256, 256>>>(dst, E, x, W1, W2, degi,
                                                        xhi, xlo, w1hi, w1lo, w2hi, w2lo);
    }
    // 2) single-pass scan -> row/cur + dinv
    scan_kernel<<<NB, 256>>>(degi, desc, row, cur, dinv, NN);
    // 3) CSR slot scatter
    slot_scatter_kernel<<<(E + 255) / 256, 256>>>(src, dst, cur, csr, E);

    // 4) GEMM1 (cp.async double-buffered pure-copy bf16x3)
    mma_gemm1<<<(NN + 127) / 128, 256, SMEM1>>>(xhi, xlo, w1hi, w1lo, h2, dinv, NN);
    // 5) pull layer 1
    pull128_kernel<<<(NN * 32 + 255) / 256, 256>>>(h2, row, csr, agg1, NN);
    // 6) GEMM2
    mma_gemm2<<<(NN + 127) / 128, 256, SMEM2>>>(agg1, w2hi, w2lo, z2, dinv, b1, NN);
    // 7) pull layer 2 + bias; tail blocks reset degi/desc
    {
        const int PULL_BLOCKS = (NN * 32 + 255) / 256;
        const int ZERO_BLOCKS = (NN + NB + 2047) / 2048;
        pull64_kernel<<<PULL_BLOCKS + ZERO_BLOCKS, 256>>>(
            z2, row, csr, dinv, b2, out, NN, PULL_BLOCKS, degi, desc);
    }
}

// round 11
// speedup vs baseline: 1.0158x; 1.0158x over previous
#include <cuda_runtime.h>
#include <cuda_bf16.h>
#include <cuda_fp16.h>
#include <cstdint>

#define NN     50000
#define IN_C   256
#define HID_C  128
#define OUT_C  64
#define E_MAX  800000
#define NB     ((NN + 255) / 256)   // 196 scan blocks

// ---------------- scratch ----------------
__device__ __align__(16) float g_dinv[NN];
__device__ __align__(16) int   g_degi[NN];          // zeroed at END of each call
__device__ __align__(16) int   g_row [NN + 1];
__device__ __align__(16) int   g_cur [NN];
__device__ __align__(16) unsigned long long g_desc[NB];  // zeroed at END of each call
__device__ __align__(16) int   g_csr [E_MAX];
__device__ __align__(16) __half g_h2  [NN * HID_C];
__device__ __align__(16) __half g_agg1[NN * HID_C];
__device__ __align__(16) __half g_z2  [NN * OUT_C];
__device__ __align__(16) __nv_bfloat16 g_w1hi[HID_C * IN_C];
__device__ __align__(16) __nv_bfloat16 g_w1lo[HID_C * IN_C];
__device__ __align__(16) __nv_bfloat16 g_w2hi[OUT_C * HID_C];
__device__ __align__(16) __nv_bfloat16 g_w2lo[OUT_C * HID_C];

// ---------------- prep: deg histogram + W conversion (R9 style) --------------
__global__ void prep_count_kernel(const int* __restrict__ dst, int E,
                                  const float* __restrict__ W1, const float* __restrict__ W2,
                                  int* __restrict__ degi,
                                  __nv_bfloat16* __restrict__ w1hi, __nv_bfloat16* __restrict__ w1lo,
                                  __nv_bfloat16* __restrict__ w2hi, __nv_bfloat16* __restrict__ w2lo) {
    const int W1N = IN_C * HID_C;
    const int W2N = HID_C * OUT_C;
    int idx = blockIdx.x * blockDim.x + threadIdx.x;
    if (idx < E) {
        atomicAdd(&degi[dst[idx]], 1);
    } else if (idx < E + W1N) {
        int i = idx - E;
        int n = i / IN_C, k = i % IN_C;
        float v = W1[(long long)k * HID_C + n];
        __nv_bfloat16 hi = __float2bfloat16_rn(v);
        w1hi[i] = hi;
        w1lo[i] = __float2bfloat16_rn(v - __bfloat162float(hi));
    } else if (idx < E + W1N + W2N) {
        int i = idx - E - W1N;
        int n = i / HID_C, k = i % HID_C;
        float v = W2[(long long)k * OUT_C + n];
        __nv_bfloat16 hi = __float2bfloat16_rn(v);
        w2hi[i] = hi;
        w2lo[i] = __float2bfloat16_rn(v - __bfloat162float(hi));
    }
}

// ---------------- single-pass scan (decoupled lookback) + dinv ---------------
__global__ void scan_kernel(const int* __restrict__ deg, unsigned long long* __restrict__ desc,
                            int* __restrict__ row, int* __restrict__ cur,
                            float* __restrict__ dinv, int n) {
    __shared__ int s[256];
    __shared__ int s_carry;
    const int bid = blockIdx.x;
    const int t   = threadIdx.x;
    const int i   = bid * 256 + t;
    int v = (i < n) ? deg[i] : 0;
    s[t] = v;
    __syncthreads();
    #pragma unroll
    for (int off = 1; off < 256; off <<= 1) {
        int u = (t >= off) ? s[t - off] : 0;
        __syncthreads();
        s[t] += u;
        __syncthreads();
    }
    int total = s[255];
    if (t == 0) {
        unsigned long long d = ((unsigned long long)(bid == 0 ? 2u : 1u) << 32)
                             | (unsigned int)total;
        atomicExch(&desc[bid], d);
        if (bid == 0) s_carry = 0;
    }
    if (bid > 0 && t < 32) {
        int carry = 0;
        int j = bid - 1;
        while (true) {
            int jj = j - t;
            unsigned long long d = 0ULL;
            if (jj >= 0) d = *((volatile unsigned long long*)&desc[jj]);
            int st  = (int)(d >> 32);
            int val = (int)(d & 0xffffffffu);
            unsigned ready = __ballot_sync(0xffffffffu, (jj < 0) || st >= 1);
            if (ready != 0xffffffffu) continue;
            unsigned pmask = __ballot_sync(0xffffffffu, (jj >= 0) && st == 2);
            if (pmask) {
                int lp = __ffs(pmask) - 1;
                int contrib = (jj >= 0 && t <= lp) ? val : 0;
                #pragma unroll
                for (int o = 16; o > 0; o >>= 1)
                    contrib += __shfl_down_sync(0xffffffffu, contrib, o);
                carry += __shfl_sync(0xffffffffu, contrib, 0);
                break;
            } else {
                int contrib = (jj >= 0) ? val : 0;
                #pragma unroll
                for (int o = 16; o > 0; o >>= 1)
                    contrib += __shfl_down_sync(0xffffffffu, contrib, o);
                carry += __shfl_sync(0xffffffffu, contrib, 0);
                j -= 32;
                if (j < 0) break;
            }
        }
        if (t == 0) {
            atomicExch(&desc[bid], (2ULL << 32) | (unsigned int)(carry + total));
            s_carry = carry;
        }
    }
    __syncthreads();
    int carry = s_carry;
    if (i < n) {
        int excl = carry + s[t] - v;
        row[i] = excl;
        cur[i] = excl;
        dinv[i] = rsqrtf((float)v + 1.0f);
        if (i == n - 1) row[n] = excl + v;
    }
}

__global__ void slot_scatter_kernel(const int* __restrict__ src, const int* __restrict__ dst,
                                    int* __restrict__ cur, int* __restrict__ csr, int E) {
    int e = blockIdx.x * blockDim.x + threadIdx.x;
    if (e < E) {
        int pos = atomicAdd(&cur[dst[e]], 1);
        csr[pos] = src[e];
    }
}

// ---------------- mma.sync helper -------------------------------------------
__device__ __forceinline__ void mma16816(float c[4], const uint32_t a[4], const uint32_t b[2]) {
    asm volatile(
        "mma.sync.aligned.m16n8k16.row.col.f32.bf16.bf16.f32 "
        "{%0,%1,%2,%3}, {%4,%5,%6,%7}, {%8,%9}, {%0,%1,%2,%3};"
        : "+f"(c[0]), "+f"(c[1]), "+f"(c[2]), "+f"(c[3])
        : "r"(a[0]), "r"(a[1]), "r"(a[2]), "r"(a[3]), "r"(b[0]), "r"(b[1]));
}

// ---------------- bf16x3 HMMA GEMM, BM=64 (3 CTAs/SM) ------------------------
// TRANS=false: A fp32, op(A)=A             (GEMM1)
// TRANS=true:  A fp16, op(A)=relu(bias + dinv[r]*A)  (GEMM2)
// Output C fp16 = dinv[r]*acc. 8 warps = 4 m-groups(16) x 2 n-groups(BN/2).
template<int BN, int KTOT, bool TRANS>
__global__ void __launch_bounds__(256, 3)
mma_gemm(const void* __restrict__ Av,
         const __nv_bfloat16* __restrict__ Whi, const __nv_bfloat16* __restrict__ Wlo,
         __half* __restrict__ C,
         const float* __restrict__ dinv, const float* __restrict__ bias, int M) {
    const int BM = 64, BK = 64, LD = 72;
    const int NW = BN / 2;
    const int NT = NW / 8;
    const int A_HI = 0;
    const int A_LO = A_HI + BM * LD * 2;
    const int B_HI = A_LO + BM * LD * 2;
    const int B_LO = B_HI + BN * LD * 2;

    extern __shared__ __align__(16) char smem[];
    __nv_bfloat16* as_hi = reinterpret_cast<__nv_bfloat16*>(smem + A_HI);
    __nv_bfloat16* as_lo = reinterpret_cast<__nv_bfloat16*>(smem + A_LO);
    __nv_bfloat16* bs_hi = reinterpret_cast<__nv_bfloat16*>(smem + B_HI);
    __nv_bfloat16* bs_lo = reinterpret_cast<__nv_bfloat16*>(smem + B_LO);

    const int tid  = threadIdx.x;
    const int wid  = tid >> 5;
    const int lane = tid & 31;
    const int g    = lane >> 2;
    const int t    = lane & 3;
    const int wm   = wid & 3;      // 4 m-groups of 16 rows
    const int wn   = wid >> 2;     // 2 n-groups of NW cols
    const int row0 = blockIdx.x * BM;

    float acc[NT][4];
    #pragma unroll
    for (int nt = 0; nt < NT; nt++)
        #pragma unroll
        for (int q = 0; q < 4; q++) acc[nt][q] = 0.0f;

    for (int kc = 0; kc < KTOT; kc += BK) {
        // ---- A tile: BM*BK/4 = 1024 quads, 4 iters ----
        #pragma unroll
        for (int it = 0; it < (BM * BK / 4) / 256; it++) {
            int idx = tid + it * 256;
            int row = idx >> 4;             // 0..63
            int k4  = (idx & 15) * 4;
            int gr  = row0 + row;
            float4 v = make_float4(0.f, 0.f, 0.f, 0.f);
            if (gr < M) {
                if constexpr (TRANS) {
                    const __half* Ah = reinterpret_cast<const __half*>(Av);
                    uint2 u = *reinterpret_cast<const uint2*>(Ah + (long long)gr * KTOT + kc + k4);
                    float2 f0 = __half22float2(*reinterpret_cast<__half2*>(&u.x));
                    float2 f1 = __half22float2(*reinterpret_cast<__half2*>(&u.y));
                    float di = dinv[gr];
                    float4 bb = *reinterpret_cast<const float4*>(bias + kc + k4);
                    v.x = fmaxf(fmaf(di, f0.x, bb.x), 0.f);
                    v.y = fmaxf(fmaf(di, f0.y, bb.y), 0.f);
                    v.z = fmaxf(fmaf(di, f1.x, bb.z), 0.f);
                    v.w = fmaxf(fmaf(di, f1.y, bb.w), 0.f);
                } else {
                    const float* Af = reinterpret_cast<const float*>(Av);
                    v = *reinterpret_cast<const float4*>(Af + (long long)gr * KTOT + kc + k4);
                }
            }
            __nv_bfloat162 h01 = __floats2bfloat162_rn(v.x, v.y);
            __nv_bfloat162 h23 = __floats2bfloat162_rn(v.z, v.w);
            float lx = v.x - __bfloat162float(__low2bfloat16(h01));
            float ly = v.y - __bfloat162float(__high2bfloat16(h01));
            float lz = v.z - __bfloat162float(__low2bfloat16(h23));
            float lw = v.w - __bfloat162float(__high2bfloat16(h23));
            __nv_bfloat162 l01 = __floats2bfloat162_rn(lx, ly);
            __nv_bfloat162 l23 = __floats2bfloat162_rn(lz, lw);
            int off = row * LD + k4;
            *reinterpret_cast<uint2*>(as_hi + off) =
                make_uint2(*reinterpret_cast<uint32_t*>(&h01), *reinterpret_cast<uint32_t*>(&h23));
            *reinterpret_cast<uint2*>(as_lo + off) =
                make_uint2(*reinterpret_cast<uint32_t*>(&l01), *reinterpret_cast<uint32_t*>(&l23));
        }
        // ---- B tile ----
        #pragma unroll
        for (int it = 0; it < (BN * BK / 4) / 256; it++) {
            int idx = tid + it * 256;
            int n  = idx >> 4;
            int k4 = (idx & 15) * 4;
            uint2 wh = *reinterpret_cast<const uint2*>(Whi + (long long)n * KTOT + kc + k4);
            uint2 wl = *reinterpret_cast<const uint2*>(Wlo + (long long)n * KTOT + kc + k4);
            int off = n * LD + k4;
            *reinterpret_cast<uint2*>(bs_hi + off) = wh;
            *reinterpret_cast<uint2*>(bs_lo + off) = wl;
        }
        __syncthreads();

        #pragma unroll
        for (int kk = 0; kk < BK; kk += 16) {
            uint32_t ah[4], al[4];
            int ar = wm * 16;
            int o00 = (ar + g) * LD + kk + 2 * t;
            int o10 = (ar + 8 + g) * LD + kk + 2 * t;
            ah[0] = *reinterpret_cast<const uint32_t*>(as_hi + o00);
            ah[1] = *reinterpret_cast<const uint32_t*>(as_hi + o10);
            ah[2] = *reinterpret_cast<const uint32_t*>(as_hi + o00 + 8);
            ah[3] = *reinterpret_cast<const uint32_t*>(as_hi + o10 + 8);
            al[0] = *reinterpret_cast<const uint32_t*>(as_lo + o00);
            al[1] = *reinterpret_cast<const uint32_t*>(as_lo + o10);
            al[2] = *reinterpret_cast<const uint32_t*>(as_lo + o00 + 8);
            al[3] = *reinterpret_cast<const uint32_t*>(as_lo + o10 + 8);
            #pragma unroll
            for (int nt = 0; nt < NT; nt++) {
                int bn = wn * NW + nt * 8 + g;
                int ob = bn * LD + kk + 2 * t;
                uint32_t bh[2], bl[2];
                bh[0] = *reinterpret_cast<const uint32_t*>(bs_hi + ob);
                bh[1] = *reinterpret_cast<const uint32_t*>(bs_hi + ob + 8);
                bl[0] = *reinterpret_cast<const uint32_t*>(bs_lo + ob);
                bl[1] = *reinterpret_cast<const uint32_t*>(bs_lo + ob + 8);
                mma16816(acc[nt], ah, bh);
                mma16816(acc[nt], ah, bl);
                mma16816(acc[nt], al, bh);
            }
        }
        __syncthreads();
    }

    // ---- epilogue ----
    int r0 = row0 + wm * 16 + g;
    int r1 = r0 + 8;
    float s0 = (r0 < M) ? dinv[r0] : 0.0f;
    float s1 = (r1 < M) ? dinv[r1] : 0.0f;
    #pragma unroll
    for (int nt = 0; nt < NT; nt++) {
        int cc = wn * NW + nt * 8 + 2 * t;
        if (r0 < M)
            *reinterpret_cast<__half2*>(C + (long long)r0 * BN + cc) =
                __floats2half2_rn(s0 * acc[nt][0], s0 * acc[nt][1]);
        if (r1 < M)
            *reinterpret_cast<__half2*>(C + (long long)r1 * BN + cc) =
                __floats2half2_rn(s1 * acc[nt][2], s1 * acc[nt][3]);
    }
}

// ---------------- pull layer 1 (fp16): agg1[d] = h2[d] + sum h2[src] ---------
__global__ void pull128_kernel(const __half* __restrict__ h2,
                               const int* __restrict__ row, const int* __restrict__ csr,
                               __half* __restrict__ agg, int n) {
    int gw = (blockIdx.x * blockDim.x + threadIdx.x) >> 5;
    int lane = threadIdx.x & 31;
    if (gw >= n) return;
    long long base = (long long)gw * HID_C + lane * 4;
    uint2 su = *reinterpret_cast<const uint2*>(h2 + base);
    float2 sf0 = __half22float2(*reinterpret_cast<__half2*>(&su.x));
    float2 sf1 = __half22float2(*reinterpret_cast<__half2*>(&su.y));
    float4 a = make_float4(sf0.x, sf0.y, sf1.x, sf1.y);
    int beg = row[gw], end = row[gw + 1];
    int j = beg;
    for (; j + 3 < end; j += 4) {
        int s0 = csr[j], s1 = csr[j + 1], s2 = csr[j + 2], s3 = csr[j + 3];
        uint2 u0 = *reinterpret_cast<const uint2*>(h2 + (long long)s0 * HID_C + lane * 4);
        uint2 u1 = *reinterpret_cast<const uint2*>(h2 + (long long)s1 * HID_C + lane * 4);
        uint2 u2 = *reinterpret_cast<const uint2*>(h2 + (long long)s2 * HID_C + lane * 4);
        uint2 u3 = *reinterpret_cast<const uint2*>(h2 + (long long)s3 * HID_C + lane * 4);
        float2 f;
        f = __half22float2(*reinterpret_cast<__half2*>(&u0.x)); a.x += f.x; a.y += f.y;
        f = __half22float2(*reinterpret_cast<__half2*>(&u0.y)); a.z += f.x; a.w += f.y;
        f = __half22float2(*reinterpret_cast<__half2*>(&u1.x)); a.x += f.x; a.y += f.y;
        f = __half22float2(*reinterpret_cast<__half2*>(&u1.y)); a.z += f.x; a.w += f.y;
        f = __half22float2(*reinterpret_cast<__half2*>(&u2.x)); a.x += f.x; a.y += f.y;
        f = __half22float2(*reinterpret_cast<__half2*>(&u2.y)); a.z += f.x; a.w += f.y;
        f = __half22float2(*reinterpret_cast<__half2*>(&u3.x)); a.x += f.x; a.y += f.y;
        f = __half22float2(*reinterpret_cast<__half2*>(&u3.y)); a.z += f.x; a.w += f.y;
    }
    for (; j < end; j++) {
        int s0 = csr[j];
        uint2 u0 = *reinterpret_cast<const uint2*>(h2 + (long long)s0 * HID_C + lane * 4);
        float2 f;
        f = __half22float2(*reinterpret_cast<__half2*>(&u0.x)); a.x += f.x; a.y += f.y;
        f = __half22float2(*reinterpret_cast<__half2*>(&u0.y)); a.z += f.x; a.w += f.y;
    }
    __half2 o0 = __floats2half2_rn(a.x, a.y);
    __half2 o1 = __floats2half2_rn(a.z, a.w);
    *reinterpret_cast<uint2*>(agg + base) =
        make_uint2(*reinterpret_cast<uint32_t*>(&o0), *reinterpret_cast<uint32_t*>(&o1));
}

// ---------------- pull layer 2 (fp16) + degi/desc reset tail -----------------
__global__ void pull64_kernel(const __half* __restrict__ z2,
                              const int* __restrict__ row, const int* __restrict__ csr,
                              const float* __restrict__ dinv, const float* __restrict__ b2,
                              float* __restrict__ out, int n,
                              int pull_blocks, int* __restrict__ degi,
                              unsigned long long* __restrict__ desc) {
    if ((int)blockIdx.x >= pull_blocks) {
        int base = ((int)blockIdx.x - pull_blocks) * 2048 + threadIdx.x * 8;
        #pragma unroll
        for (int k = 0; k < 8; k++) {
            int i = base + k;
            if (i < NN) degi[i] = 0;
            else if (i - NN < NB) desc[i - NN] = 0ULL;
        }
        return;
    }
    int gw = (blockIdx.x * blockDim.x + threadIdx.x) >> 5;
    int lane = threadIdx.x & 31;
    if (gw >= n) return;
    long long base = (long long)gw * OUT_C + lane * 2;
    float2 a = __half22float2(*reinterpret_cast<const __half2*>(z2 + base));
    int beg = row[gw], end = row[gw + 1];
    int j = beg;
    for (; j + 3 < end; j += 4) {
        int s0 = csr[j], s1 = csr[j + 1], s2 = csr[j + 2], s3 = csr[j + 3];
        float2 f0 = __half22float2(*reinterpret_cast<const __half2*>(z2 + (long long)s0 * OUT_C + lane * 2));
        float2 f1 = __half22float2(*reinterpret_cast<const __half2*>(z2 + (long long)s1 * OUT_C + lane * 2));
        float2 f2 = __half22float2(*reinterpret_cast<const __half2*>(z2 + (long long)s2 * OUT_C + lane * 2));
        float2 f3 = __half22float2(*reinterpret_cast<const __half2*>(z2 + (long long)s3 * OUT_C + lane * 2));
        a.x += (f0.x + f1.x) + (f2.x + f3.x);
        a.y += (f0.y + f1.y) + (f2.y + f3.y);
    }
    for (; j < end; j++) {
        int s0 = csr[j];
        float2 f0 = __half22float2(*reinterpret_cast<const __half2*>(z2 + (long long)s0 * OUT_C + lane * 2));
        a.x += f0.x; a.y += f0.y;
    }
    float di = dinv[gw];
    float2 bb = *reinterpret_cast<const float2*>(b2 + lane * 2);
    *reinterpret_cast<float2*>(out + base) =
        make_float2(fmaf(di, a.x, bb.x), fmaf(di, a.y, bb.y));
}

// ---------------- launch ----------------
extern "C" void kernel_launch(void* const* d_in, const int* in_sizes, int n_in,
                              void* d_out, int out_size) {
    const float* x  = (const float*)d_in[0];
    const int*   ei = (const int*)  d_in[1];
    const float* W1 = (const float*)d_in[2];
    const float* b1 = (const float*)d_in[3];
    const float* W2 = (const float*)d_in[4];
    const float* b2 = (const float*)d_in[5];
    float* out = (float*)d_out;

    const int E = in_sizes[1] / 2;
    const int* src = ei;
    const int* dst = ei + E;

    float *dinv;
    int *degi, *row, *cur, *csr;
    unsigned long long* desc;
    __half *h2, *agg1, *z2;
    __nv_bfloat16 *w1hi, *w1lo, *w2hi, *w2lo;
    cudaGetSymbolAddress((void**)&dinv, g_dinv);
    cudaGetSymbolAddress((void**)&degi, g_degi);
    cudaGetSymbolAddress((void**)&row,  g_row);
    cudaGetSymbolAddress((void**)&cur,  g_cur);
    cudaGetSymbolAddress((void**)&desc, g_desc);
    cudaGetSymbolAddress((void**)&csr,  g_csr);
    cudaGetSymbolAddress((void**)&h2,   g_h2);
    cudaGetSymbolAddress((void**)&agg1, g_agg1);
    cudaGetSymbolAddress((void**)&z2,   g_z2);
    cudaGetSymbolAddress((void**)&w1hi, g_w1hi);
    cudaGetSymbolAddress((void**)&w1lo, g_w1lo);
    cudaGetSymbolAddress((void**)&w2hi, g_w2hi);
    cudaGetSymbolAddress((void**)&w2lo, g_w2lo);

    const int LD = 72;
    const int SMEM1 = 2 * 64 * LD * 2 + 2 * 128 * LD * 2;    // 55296 B
    const int SMEM2 = 2 * 64 * LD * 2 + 2 * 64 * LD * 2;     // 36864 B
    cudaFuncSetAttribute(mma_gemm<HID_C, IN_C, false>,
                         cudaFuncAttributeMaxDynamicSharedMemorySize, SMEM1);
    cudaFuncSetAttribute(mma_gemm<OUT_C, HID_C, true>,
                         cudaFuncAttributeMaxDynamicSharedMemorySize, SMEM2);

    // 1) prep: degree histogram + W conversion
    {
        int total = E + IN_C * HID_C + HID_C * OUT_C;
        prep_count_kernel<<<(total + 255) / 256, 256>>>(dst, E, W1, W2, degi,
                                                        w1hi, w1lo, w2hi, w2lo);
    }
    // 2) single-pass scan -> row/cur + dinv
    scan_kernel<<<NB, 256>>>(degi, desc, row, cur, dinv, NN);
    // 3) CSR slot scatter
    slot_scatter_kernel<<<(E + 255) / 256, 256>>>(src, dst, cur, csr, E);

    // 4) GEMM1 (BM=64, 3 CTAs/SM): h2 = fp16( dinv * (x @ W1) )
    mma_gemm<HID_C, IN_C, false><<<(NN + 63) / 64, 256, SMEM1>>>(
        x, w1hi, w1lo, h2, dinv, nullptr, NN);
    // 5) pull layer 1
    pull128_kernel<<<(NN * 32 + 255) / 256, 256>>>(h2, row, csr, agg1, NN);
    // 6) GEMM2 (BM=64): z2 = fp16( dinv * (relu(b1 + dinv*agg1) @ W2) )
    mma_gemm<OUT_C, HID_C, true><<<(NN + 63) / 64, 256, SMEM2>>>(
        agg1, w2hi, w2lo, z2, dinv, b1, NN);
    // 7) pull layer 2 + bias; tail blocks reset degi/desc
    {
        const int PULL_BLOCKS = (NN * 32 + 255) / 256;
        const int ZERO_BLOCKS = (NN + NB + 2047) / 2048;
        pull64_kernel<<<PULL_BLOCKS + ZERO_BLOCKS, 256>>>(
            z2, row, csr, dinv, b2, out, NN, PULL_BLOCKS, degi, desc);
    }
}

// round 12
// speedup vs baseline: 1.0870x; 1.0701x over previous
#include <cuda_runtime.h>
#include <cuda_bf16.h>
#include <cuda_fp16.h>
#include <cstdint>

#define NN     50000
#define IN_C   256
#define HID_C  128
#define OUT_C  64
#define E_MAX  800000
#define NB     ((NN + 255) / 256)   // 196 scan blocks

// ---------------- scratch ----------------
__device__ __align__(16) float g_dinv[NN];
__device__ __align__(16) int   g_degi[NN];          // zeroed at END of each call
__device__ __align__(16) int   g_row [NN + 1];
__device__ __align__(16) int   g_cur [NN];
__device__ __align__(16) unsigned long long g_desc[NB];  // zeroed at END of each call
__device__ __align__(16) int   g_csr [E_MAX];
__device__ __align__(16) __half g_h2  [NN * HID_C];
__device__ __align__(16) __half g_agg1[NN * HID_C];
__device__ __align__(16) __half g_z2  [NN * OUT_C];
__device__ __align__(16) __nv_bfloat16 g_w1hi[HID_C * IN_C];
__device__ __align__(16) __nv_bfloat16 g_w1lo[HID_C * IN_C];
__device__ __align__(16) __nv_bfloat16 g_w2hi[OUT_C * HID_C];
__device__ __align__(16) __nv_bfloat16 g_w2lo[OUT_C * HID_C];

__device__ __forceinline__ uint32_t smem_u32(const void* p) {
    uint32_t a;
    asm("{ .reg .u64 t; cvta.to.shared.u64 t, %1; cvt.u32.u64 %0, t; }" : "=r"(a) : "l"(p));
    return a;
}
__device__ __forceinline__ void ldsm_x4(uint32_t (&r)[4], uint32_t saddr) {
    asm volatile("ldmatrix.sync.aligned.m8n8.x4.shared.b16 {%0,%1,%2,%3}, [%4];"
        : "=r"(r[0]), "=r"(r[1]), "=r"(r[2]), "=r"(r[3]) : "r"(saddr));
}

// ---------------- prep: deg histogram + W conversion --------------------------
__global__ void prep_count_kernel(const int* __restrict__ dst, int E,
                                  const float* __restrict__ W1, const float* __restrict__ W2,
                                  int* __restrict__ degi,
                                  __nv_bfloat16* __restrict__ w1hi, __nv_bfloat16* __restrict__ w1lo,
                                  __nv_bfloat16* __restrict__ w2hi, __nv_bfloat16* __restrict__ w2lo) {
    const int W1N = IN_C * HID_C;
    const int W2N = HID_C * OUT_C;
    int idx = blockIdx.x * blockDim.x + threadIdx.x;
    if (idx < E) {
        atomicAdd(&degi[dst[idx]], 1);
    } else if (idx < E + W1N) {
        int i = idx - E;
        int n = i / IN_C, k = i % IN_C;
        float v = W1[(long long)k * HID_C + n];
        __nv_bfloat16 hi = __float2bfloat16_rn(v);
        w1hi[i] = hi;
        w1lo[i] = __float2bfloat16_rn(v - __bfloat162float(hi));
    } else if (idx < E + W1N + W2N) {
        int i = idx - E - W1N;
        int n = i / HID_C, k = i % HID_C;
        float v = W2[(long long)k * OUT_C + n];
        __nv_bfloat16 hi = __float2bfloat16_rn(v);
        w2hi[i] = hi;
        w2lo[i] = __float2bfloat16_rn(v - __bfloat162float(hi));
    }
}

// ---------------- single-pass scan (decoupled lookback) + dinv ---------------
__global__ void scan_kernel(const int* __restrict__ deg, unsigned long long* __restrict__ desc,
                            int* __restrict__ row, int* __restrict__ cur,
                            float* __restrict__ dinv, int n) {
    __shared__ int s[256];
    __shared__ int s_carry;
    const int bid = blockIdx.x;
    const int t   = threadIdx.x;
    const int i   = bid * 256 + t;
    int v = (i < n) ? deg[i] : 0;
    s[t] = v;
    __syncthreads();
    #pragma unroll
    for (int off = 1; off < 256; off <<= 1) {
        int u = (t >= off) ? s[t - off] : 0;
        __syncthreads();
        s[t] += u;
        __syncthreads();
    }
    int total = s[255];
    if (t == 0) {
        unsigned long long d = ((unsigned long long)(bid == 0 ? 2u : 1u) << 32)
                             | (unsigned int)total;
        atomicExch(&desc[bid], d);
        if (bid == 0) s_carry = 0;
    }
    if (bid > 0 && t < 32) {
        int carry = 0;
        int j = bid - 1;
        while (true) {
            int jj = j - t;
            unsigned long long d = 0ULL;
            if (jj >= 0) d = *((volatile unsigned long long*)&desc[jj]);
            int st  = (int)(d >> 32);
            int val = (int)(d & 0xffffffffu);
            unsigned ready = __ballot_sync(0xffffffffu, (jj < 0) || st >= 1);
            if (ready != 0xffffffffu) continue;
            unsigned pmask = __ballot_sync(0xffffffffu, (jj >= 0) && st == 2);
            if (pmask) {
                int lp = __ffs(pmask) - 1;
                int contrib = (jj >= 0 && t <= lp) ? val : 0;
                #pragma unroll
                for (int o = 16; o > 0; o >>= 1)
                    contrib += __shfl_down_sync(0xffffffffu, contrib, o);
                carry += __shfl_sync(0xffffffffu, contrib, 0);
                break;
            } else {
                int contrib = (jj >= 0) ? val : 0;
                #pragma unroll
                for (int o = 16; o > 0; o >>= 1)
                    contrib += __shfl_down_sync(0xffffffffu, contrib, o);
                carry += __shfl_sync(0xffffffffu, contrib, 0);
                j -= 32;
                if (j < 0) break;
            }
        }
        if (t == 0) {
            atomicExch(&desc[bid], (2ULL << 32) | (unsigned int)(carry + total));
            s_carry = carry;
        }
    }
    __syncthreads();
    int carry = s_carry;
    if (i < n) {
        int excl = carry + s[t] - v;
        row[i] = excl;
        cur[i] = excl;
        dinv[i] = rsqrtf((float)v + 1.0f);
        if (i == n - 1) row[n] = excl + v;
    }
}

__global__ void slot_scatter_kernel(const int* __restrict__ src, const int* __restrict__ dst,
                                    int* __restrict__ cur, int* __restrict__ csr, int E) {
    int e = blockIdx.x * blockDim.x + threadIdx.x;
    if (e < E) {
        int pos = atomicAdd(&cur[dst[e]], 1);
        csr[pos] = src[e];
    }
}

// ---------------- mma.sync helper -------------------------------------------
__device__ __forceinline__ void mma16816(float c[4], const uint32_t a[4], const uint32_t b[2]) {
    asm volatile(
        "mma.sync.aligned.m16n8k16.row.col.f32.bf16.bf16.f32 "
        "{%0,%1,%2,%3}, {%4,%5,%6,%7}, {%8,%9}, {%0,%1,%2,%3};"
        : "+f"(c[0]), "+f"(c[1]), "+f"(c[2]), "+f"(c[3])
        : "r"(a[0]), "r"(a[1]), "r"(a[2]), "r"(a[3]), "r"(b[0]), "r"(b[1]));
}

// ---------------- bf16x3 HMMA GEMM with ldmatrix fragment loads ---------------
// BM=128, BK=64, LD=72 (144B rows: 16B-aligned, conflict-free for LDSM).
// TRANS=false: A fp32, op(A)=A ; TRANS=true: A fp16, op(A)=relu(bias+dinv*A).
// C fp16 = dinv[r]*acc. 8 warps = 4 m-groups(32 rows, 2 m-tiles) x 2 n-groups.
template<int BN, int KTOT, bool TRANS>
__global__ void __launch_bounds__(256, 2)
mma_gemm(const void* __restrict__ Av,
         const __nv_bfloat16* __restrict__ Whi, const __nv_bfloat16* __restrict__ Wlo,
         __half* __restrict__ C,
         const float* __restrict__ dinv, const float* __restrict__ bias, int M) {
    const int BM = 128, BK = 64, LD = 72;
    const int NW = BN / 2;
    const int NT = NW / 8;
    const int A_HI = 0;
    const int A_LO = A_HI + BM * LD * 2;
    const int B_HI = A_LO + BM * LD * 2;
    const int B_LO = B_HI + BN * LD * 2;

    extern __shared__ __align__(16) char smem[];
    __nv_bfloat16* as_hi = reinterpret_cast<__nv_bfloat16*>(smem + A_HI);
    __nv_bfloat16* as_lo = reinterpret_cast<__nv_bfloat16*>(smem + A_LO);
    __nv_bfloat16* bs_hi = reinterpret_cast<__nv_bfloat16*>(smem + B_HI);
    __nv_bfloat16* bs_lo = reinterpret_cast<__nv_bfloat16*>(smem + B_LO);
    const uint32_t s_ahi = smem_u32(as_hi);
    const uint32_t s_alo = smem_u32(as_lo);
    const uint32_t s_bhi = smem_u32(bs_hi);
    const uint32_t s_blo = smem_u32(bs_lo);

    const int tid  = threadIdx.x;
    const int wid  = tid >> 5;
    const int lane = tid & 31;
    const int g    = lane >> 2;
    const int t    = lane & 3;
    const int wm   = wid & 3;      // m-group: 32 rows (2 x 16 tiles)
    const int wn   = wid >> 2;     // n-group: NW cols
    const int row0 = blockIdx.x * BM;

    float acc[2][NT][4];
    #pragma unroll
    for (int mt = 0; mt < 2; mt++)
        #pragma unroll
        for (int nt = 0; nt < NT; nt++)
            #pragma unroll
            for (int q = 0; q < 4; q++) acc[mt][nt][q] = 0.0f;

    // precomputed LDSM lane-offsets (byte offsets within tile)
    const uint32_t a_lrow = (uint32_t)(lane & 15);
    const uint32_t a_lk   = (uint32_t)((lane >> 4) << 3);
    const int b_msel = lane >> 3;
    const uint32_t b_lrow = (uint32_t)((b_msel & 2) ? 8 : 0) + (uint32_t)(lane & 7);
    const uint32_t b_lk   = (uint32_t)((b_msel & 1) << 3);

    for (int kc = 0; kc < KTOT; kc += BK) {
        // ---- A tile fill: load/transform -> bf16 hi/lo ----
        #pragma unroll
        for (int it = 0; it < (BM * BK / 4) / 256; it++) {
            int idx = tid + it * 256;
            int row = idx >> 4;
            int k4  = (idx & 15) * 4;
            int gr  = row0 + row;
            float4 v = make_float4(0.f, 0.f, 0.f, 0.f);
            if (gr < M) {
                if constexpr (TRANS) {
                    const __half* Ah = reinterpret_cast<const __half*>(Av);
                    uint2 u = *reinterpret_cast<const uint2*>(Ah + (long long)gr * KTOT + kc + k4);
                    float2 f0 = __half22float2(*reinterpret_cast<__half2*>(&u.x));
                    float2 f1 = __half22float2(*reinterpret_cast<__half2*>(&u.y));
                    float di = dinv[gr];
                    float4 bb = *reinterpret_cast<const float4*>(bias + kc + k4);
                    v.x = fmaxf(fmaf(di, f0.x, bb.x), 0.f);
                    v.y = fmaxf(fmaf(di, f0.y, bb.y), 0.f);
                    v.z = fmaxf(fmaf(di, f1.x, bb.z), 0.f);
                    v.w = fmaxf(fmaf(di, f1.y, bb.w), 0.f);
                } else {
                    const float* Af = reinterpret_cast<const float*>(Av);
                    v = *reinterpret_cast<const float4*>(Af + (long long)gr * KTOT + kc + k4);
                }
            }
            __nv_bfloat162 h01 = __floats2bfloat162_rn(v.x, v.y);
            __nv_bfloat162 h23 = __floats2bfloat162_rn(v.z, v.w);
            float lx = v.x - __bfloat162float(__low2bfloat16(h01));
            float ly = v.y - __bfloat162float(__high2bfloat16(h01));
            float lz = v.z - __bfloat162float(__low2bfloat16(h23));
            float lw = v.w - __bfloat162float(__high2bfloat16(h23));
            __nv_bfloat162 l01 = __floats2bfloat162_rn(lx, ly);
            __nv_bfloat162 l23 = __floats2bfloat162_rn(lz, lw);
            int off = row * LD + k4;
            *reinterpret_cast<uint2*>(as_hi + off) =
                make_uint2(*reinterpret_cast<uint32_t*>(&h01), *reinterpret_cast<uint32_t*>(&h23));
            *reinterpret_cast<uint2*>(as_lo + off) =
                make_uint2(*reinterpret_cast<uint32_t*>(&l01), *reinterpret_cast<uint32_t*>(&l23));
        }
        // ---- B tile fill ----
        #pragma unroll
        for (int it = 0; it < (BN * BK / 4) / 256; it++) {
            int idx = tid + it * 256;
            int n  = idx >> 4;
            int k4 = (idx & 15) * 4;
            uint2 wh = *reinterpret_cast<const uint2*>(Whi + (long long)n * KTOT + kc + k4);
            uint2 wl = *reinterpret_cast<const uint2*>(Wlo + (long long)n * KTOT + kc + k4);
            int off = n * LD + k4;
            *reinterpret_cast<uint2*>(bs_hi + off) = wh;
            *reinterpret_cast<uint2*>(bs_lo + off) = wl;
        }
        __syncthreads();

        // ---- compute: ldmatrix fragments + MMA ----
        #pragma unroll
        for (int kk = 0; kk < BK; kk += 16) {
            uint32_t ah[2][4], al[2][4];
            #pragma unroll
            for (int mt = 0; mt < 2; mt++) {
                uint32_t ar = (uint32_t)(wm * 32 + mt * 16);
                uint32_t off = ((ar + a_lrow) * LD + (uint32_t)kk + a_lk) * 2;
                ldsm_x4(ah[mt], s_ahi + off);
                ldsm_x4(al[mt], s_alo + off);
            }
            #pragma unroll
            for (int p = 0; p < NT / 2; p++) {
                uint32_t bn = (uint32_t)(wn * NW + p * 16) + b_lrow;
                uint32_t boff = (bn * LD + (uint32_t)kk + b_lk) * 2;
                uint32_t bh[4], bl[4];
                ldsm_x4(bh, s_bhi + boff);
                ldsm_x4(bl, s_blo + boff);
                #pragma unroll
                for (int q = 0; q < 2; q++) {
                    uint32_t bhq[2] = {bh[2 * q], bh[2 * q + 1]};
                    uint32_t blq[2] = {bl[2 * q], bl[2 * q + 1]};
                    #pragma unroll
                    for (int mt = 0; mt < 2; mt++) {
                        mma16816(acc[mt][2 * p + q], ah[mt], bhq);
                        mma16816(acc[mt][2 * p + q], ah[mt], blq);
                        mma16816(acc[mt][2 * p + q], al[mt], bhq);
                    }
                }
            }
        }
        __syncthreads();
    }

    // ---- epilogue: scale by dinv, store fp16 ----
    #pragma unroll
    for (int mt = 0; mt < 2; mt++) {
        int r0 = row0 + wm * 32 + mt * 16 + g;
        int r1 = r0 + 8;
        float s0 = (r0 < M) ? dinv[r0] : 0.0f;
        float s1 = (r1 < M) ? dinv[r1] : 0.0f;
        #pragma unroll
        for (int nt = 0; nt < NT; nt++) {
            int cc = wn * NW + nt * 8 + 2 * t;
            if (r0 < M)
                *reinterpret_cast<__half2*>(C + (long long)r0 * BN + cc) =
                    __floats2half2_rn(s0 * acc[mt][nt][0], s0 * acc[mt][nt][1]);
            if (r1 < M)
                *reinterpret_cast<__half2*>(C + (long long)r1 * BN + cc) =
                    __floats2half2_rn(s1 * acc[mt][nt][2], s1 * acc[mt][nt][3]);
        }
    }
}

// ---------------- pull layer 1 (fp16): agg1[d] = h2[d] + sum h2[src] ---------
__global__ void pull128_kernel(const __half* __restrict__ h2,
                               const int* __restrict__ row, const int* __restrict__ csr,
                               __half* __restrict__ agg, int n) {
    int gw = (blockIdx.x * blockDim.x + threadIdx.x) >> 5;
    int lane = threadIdx.x & 31;
    if (gw >= n) return;
    long long base = (long long)gw * HID_C + lane * 4;
    uint2 su = *reinterpret_cast<const uint2*>(h2 + base);
    float2 sf0 = __half22float2(*reinterpret_cast<__half2*>(&su.x));
    float2 sf1 = __half22float2(*reinterpret_cast<__half2*>(&su.y));
    float4 a = make_float4(sf0.x, sf0.y, sf1.x, sf1.y);
    int beg = row[gw], end = row[gw + 1];
    int j = beg;
    for (; j + 3 < end; j += 4) {
        int s0 = csr[j], s1 = csr[j + 1], s2 = csr[j + 2], s3 = csr[j + 3];
        uint2 u0 = *reinterpret_cast<const uint2*>(h2 + (long long)s0 * HID_C + lane * 4);
        uint2 u1 = *reinterpret_cast<const uint2*>(h2 + (long long)s1 * HID_C + lane * 4);
        uint2 u2 = *reinterpret_cast<const uint2*>(h2 + (long long)s2 * HID_C + lane * 4);
        uint2 u3 = *reinterpret_cast<const uint2*>(h2 + (long long)s3 * HID_C + lane * 4);
        float2 f;
        f = __half22float2(*reinterpret_cast<__half2*>(&u0.x)); a.x += f.x; a.y += f.y;
        f = __half22float2(*reinterpret_cast<__half2*>(&u0.y)); a.z += f.x; a.w += f.y;
        f = __half22float2(*reinterpret_cast<__half2*>(&u1.x)); a.x += f.x; a.y += f.y;
        f = __half22float2(*reinterpret_cast<__half2*>(&u1.y)); a.z += f.x; a.w += f.y;
        f = __half22float2(*reinterpret_cast<__half2*>(&u2.x)); a.x += f.x; a.y += f.y;
        f = __half22float2(*reinterpret_cast<__half2*>(&u2.y)); a.z += f.x; a.w += f.y;
        f = __half22float2(*reinterpret_cast<__half2*>(&u3.x)); a.x += f.x; a.y += f.y;
        f = __half22float2(*reinterpret_cast<__half2*>(&u3.y)); a.z += f.x; a.w += f.y;
    }
    for (; j < end; j++) {
        int s0 = csr[j];
        uint2 u0 = *reinterpret_cast<const uint2*>(h2 + (long long)s0 * HID_C + lane * 4);
        float2 f;
        f = __half22float2(*reinterpret_cast<__half2*>(&u0.x)); a.x += f.x; a.y += f.y;
        f = __half22float2(*reinterpret_cast<__half2*>(&u0.y)); a.z += f.x; a.w += f.y;
    }
    __half2 o0 = __floats2half2_rn(a.x, a.y);
    __half2 o1 = __floats2half2_rn(a.z, a.w);
    *reinterpret_cast<uint2*>(agg + base) =
        make_uint2(*reinterpret_cast<uint32_t*>(&o0), *reinterpret_cast<uint32_t*>(&o1));
}

// ---------------- pull layer 2 (fp16) + degi/desc reset tail -----------------
__global__ void pull64_kernel(const __half* __restrict__ z2,
                              const int* __restrict__ row, const int* __restrict__ csr,
                              const float* __restrict__ dinv, const float* __restrict__ b2,
                              float* __restrict__ out, int n,
                              int pull_blocks, int* __restrict__ degi,
                              unsigned long long* __restrict__ desc) {
    if ((int)blockIdx.x >= pull_blocks) {
        int base = ((int)blockIdx.x - pull_blocks) * 2048 + threadIdx.x * 8;
        #pragma unroll
        for (int k = 0; k < 8; k++) {
            int i = base + k;
            if (i < NN) degi[i] = 0;
            else if (i - NN < NB) desc[i - NN] = 0ULL;
        }
        return;
    }
    int gw = (blockIdx.x * blockDim.x + threadIdx.x) >> 5;
    int lane = threadIdx.x & 31;
    if (gw >= n) return;
    long long base = (long long)gw * OUT_C + lane * 2;
    float2 a = __half22float2(*reinterpret_cast<const __half2*>(z2 + base));
    int beg = row[gw], end = row[gw + 1];
    int j = beg;
    for (; j + 3 < end; j += 4) {
        int s0 = csr[j], s1 = csr[j + 1], s2 = csr[j + 2], s3 = csr[j + 3];
        float2 f0 = __half22float2(*reinterpret_cast<const __half2*>(z2 + (long long)s0 * OUT_C + lane * 2));
        float2 f1 = __half22float2(*reinterpret_cast<const __half2*>(z2 + (long long)s1 * OUT_C + lane * 2));
        float2 f2 = __half22float2(*reinterpret_cast<const __half2*>(z2 + (long long)s2 * OUT_C + lane * 2));
        float2 f3 = __half22float2(*reinterpret_cast<const __half2*>(z2 + (long long)s3 * OUT_C + lane * 2));
        a.x += (f0.x + f1.x) + (f2.x + f3.x);
        a.y += (f0.y + f1.y) + (f2.y + f3.y);
    }
    for (; j < end; j++) {
        int s0 = csr[j];
        float2 f0 = __half22float2(*reinterpret_cast<const __half2*>(z2 + (long long)s0 * OUT_C + lane * 2));
        a.x += f0.x; a.y += f0.y;
    }
    float di = dinv[gw];
    float2 bb = *reinterpret_cast<const float2*>(b2 + lane * 2);
    *reinterpret_cast<float2*>(out + base) =
        make_float2(fmaf(di, a.x, bb.x), fmaf(di, a.y, bb.y));
}

// ---------------- launch ----------------
extern "C" void kernel_launch(void* const* d_in, const int* in_sizes, int n_in,
                              void* d_out, int out_size) {
    const float* x  = (const float*)d_in[0];
    const int*   ei = (const int*)  d_in[1];
    const float* W1 = (const float*)d_in[2];
    const float* b1 = (const float*)d_in[3];
    const float* W2 = (const float*)d_in[4];
    const float* b2 = (const float*)d_in[5];
    float* out = (float*)d_out;

    const int E = in_sizes[1] / 2;
    const int* src = ei;
    const int* dst = ei + E;

    float *dinv;
    int *degi, *row, *cur, *csr;
    unsigned long long* desc;
    __half *h2, *agg1, *z2;
    __nv_bfloat16 *w1hi, *w1lo, *w2hi, *w2lo;
    cudaGetSymbolAddress((void**)&dinv, g_dinv);
    cudaGetSymbolAddress((void**)&degi, g_degi);
    cudaGetSymbolAddress((void**)&row,  g_row);
    cudaGetSymbolAddress((void**)&cur,  g_cur);
    cudaGetSymbolAddress((void**)&desc, g_desc);
    cudaGetSymbolAddress((void**)&csr,  g_csr);
    cudaGetSymbolAddress((void**)&h2,   g_h2);
    cudaGetSymbolAddress((void**)&agg1, g_agg1);
    cudaGetSymbolAddress((void**)&z2,   g_z2);
    cudaGetSymbolAddress((void**)&w1hi, g_w1hi);
    cudaGetSymbolAddress((void**)&w1lo, g_w1lo);
    cudaGetSymbolAddress((void**)&w2hi, g_w2hi);
    cudaGetSymbolAddress((void**)&w2lo, g_w2lo);

    const int LD = 72;
    const int SMEM1 = 2 * 128 * LD * 2 + 2 * 128 * LD * 2;   // 73728 B
    const int SMEM2 = 2 * 128 * LD * 2 + 2 * 64 * LD * 2;    // 55296 B
    cudaFuncSetAttribute(mma_gemm<HID_C, IN_C, false>,
                         cudaFuncAttributeMaxDynamicSharedMemorySize, SMEM1);
    cudaFuncSetAttribute(mma_gemm<OUT_C, HID_C, true>,
                         cudaFuncAttributeMaxDynamicSharedMemorySize, SMEM2);

    // 1) prep: degree histogram + W conversion
    {
        int total = E + IN_C * HID_C + HID_C * OUT_C;
        prep_count_kernel<<<(total + 255) / 256, 256>>>(dst, E, W1, W2, degi,
                                                        w1hi, w1lo, w2hi, w2lo);
    }
    // 2) single-pass scan -> row/cur + dinv
    scan_kernel<<<NB, 256>>>(degi, desc, row, cur, dinv, NN);
    // 3) CSR slot scatter
    slot_scatter_kernel<<<(E + 255) / 256, 256>>>(src, dst, cur, csr, E);

    // 4) GEMM1 (ldmatrix + bf16x3 HMMA): h2 = fp16( dinv * (x @ W1) )
    mma_gemm<HID_C, IN_C, false><<<(NN + 127) / 128, 256, SMEM1>>>(
        x, w1hi, w1lo, h2, dinv, nullptr, NN);
    // 5) pull layer 1
    pull128_kernel<<<(NN * 32 + 255) / 256, 256>>>(h2, row, csr, agg1, NN);
    // 6) GEMM2: z2 = fp16( dinv * (relu(b1 + dinv*agg1) @ W2) )
    mma_gemm<OUT_C, HID_C, true><<<(NN + 127) / 128, 256, SMEM2>>>(
        agg1, w2hi, w2lo, z2, dinv, b1, NN);
    // 7) pull layer 2 + bias; tail blocks reset degi/desc
    {
        const int PULL_BLOCKS = (NN * 32 + 255) / 256;
        const int ZERO_BLOCKS = (NN + NB + 2047) / 2048;
        pull64_kernel<<<PULL_BLOCKS + ZERO_BLOCKS, 256>>>(
            z2, row, csr, dinv, b2, out, NN, PULL_BLOCKS, degi, desc);
    }
}

// round 13
// speedup vs baseline: 1.1816x; 1.0871x over previous
#include <cuda_runtime.h>
#include <cuda_bf16.h>
#include <cuda_fp16.h>
#include <cstdint>

#define NN     50000
#define IN_C   256
#define HID_C  128
#define OUT_C  64
#define E_MAX  800000
#define NB     ((NN + 255) / 256)   // 196 scan blocks

// ---------------- scratch ----------------
__device__ __align__(16) float g_dinv[NN];
__device__ __align__(16) int   g_degi[NN];          // zeroed at END of each call
__device__ __align__(16) int   g_row [NN + 1];
__device__ __align__(16) int   g_cur [NN];
__device__ __align__(16) unsigned long long g_desc[NB];  // zeroed at END of each call
__device__ __align__(16) int   g_csr [E_MAX];
__device__ __align__(16) __half g_h2  [NN * HID_C];
__device__ __align__(16) __half g_agg1[NN * HID_C];
__device__ __align__(16) __half g_z2  [NN * OUT_C];
__device__ __align__(16) __half g_w1hi[HID_C * IN_C];   // fp16 weight hi/lo, [N,K]
__device__ __align__(16) __half g_w1lo[HID_C * IN_C];
__device__ __align__(16) __half g_w2hi[OUT_C * HID_C];
__device__ __align__(16) __half g_w2lo[OUT_C * HID_C];

__device__ __forceinline__ uint32_t smem_u32(const void* p) {
    uint32_t a;
    asm("{ .reg .u64 t; cvta.to.shared.u64 t, %1; cvt.u32.u64 %0, t; }" : "=r"(a) : "l"(p));
    return a;
}
__device__ __forceinline__ void ldsm_x4(uint32_t (&r)[4], uint32_t saddr) {
    asm volatile("ldmatrix.sync.aligned.m8n8.x4.shared.b16 {%0,%1,%2,%3}, [%4];"
        : "=r"(r[0]), "=r"(r[1]), "=r"(r[2]), "=r"(r[3]) : "r"(saddr));
}

// ---------------- prep: deg histogram (x4 vectorized) + W fp16 hi/lo ---------
__global__ void prep_count_kernel(const int* __restrict__ dst, int E,
                                  const float* __restrict__ W1, const float* __restrict__ W2,
                                  int* __restrict__ degi,
                                  __half* __restrict__ w1hi, __half* __restrict__ w1lo,
                                  __half* __restrict__ w2hi, __half* __restrict__ w2lo) {
    const int EQ  = E / 4;                 // E divisible by 4 (800000)
    const int W1N = IN_C * HID_C;
    const int W2N = HID_C * OUT_C;
    int idx = blockIdx.x * blockDim.x + threadIdx.x;
    if (idx < EQ) {
        int4 d4 = reinterpret_cast<const int4*>(dst)[idx];
        atomicAdd(&degi[d4.x], 1);
        atomicAdd(&degi[d4.y], 1);
        atomicAdd(&degi[d4.z], 1);
        atomicAdd(&degi[d4.w], 1);
    } else if (idx < EQ + W1N) {
        int i = idx - EQ;
        int n = i / IN_C, k = i % IN_C;
        float v = W1[(long long)k * HID_C + n];
        __half hi = __float2half_rn(v);
        w1hi[i] = hi;
        w1lo[i] = __float2half_rn(v - __half2float(hi));
    } else if (idx < EQ + W1N + W2N) {
        int i = idx - EQ - W1N;
        int n = i / HID_C, k = i % HID_C;
        float v = W2[(long long)k * OUT_C + n];
        __half hi = __float2half_rn(v);
        w2hi[i] = hi;
        w2lo[i] = __float2half_rn(v - __half2float(hi));
    }
}

// ---------------- single-pass scan (decoupled lookback) + dinv ---------------
__global__ void scan_kernel(const int* __restrict__ deg, unsigned long long* __restrict__ desc,
                            int* __restrict__ row, int* __restrict__ cur,
                            float* __restrict__ dinv, int n) {
    __shared__ int s[256];
    __shared__ int s_carry;
    const int bid = blockIdx.x;
    const int t   = threadIdx.x;
    const int i   = bid * 256 + t;
    int v = (i < n) ? deg[i] : 0;
    s[t] = v;
    __syncthreads();
    #pragma unroll
    for (int off = 1; off < 256; off <<= 1) {
        int u = (t >= off) ? s[t - off] : 0;
        __syncthreads();
        s[t] += u;
        __syncthreads();
    }
    int total = s[255];
    if (t == 0) {
        unsigned long long d = ((unsigned long long)(bid == 0 ? 2u : 1u) << 32)
                             | (unsigned int)total;
        atomicExch(&desc[bid], d);
        if (bid == 0) s_carry = 0;
    }
    if (bid > 0 && t < 32) {
        int carry = 0;
        int j = bid - 1;
        while (true) {
            int jj = j - t;
            unsigned long long d = 0ULL;
            if (jj >= 0) d = *((volatile unsigned long long*)&desc[jj]);
            int st  = (int)(d >> 32);
            int val = (int)(d & 0xffffffffu);
            unsigned ready = __ballot_sync(0xffffffffu, (jj < 0) || st >= 1);
            if (ready != 0xffffffffu) continue;
            unsigned pmask = __ballot_sync(0xffffffffu, (jj >= 0) && st == 2);
            if (pmask) {
                int lp = __ffs(pmask) - 1;
                int contrib = (jj >= 0 && t <= lp) ? val : 0;
                #pragma unroll
                for (int o = 16; o > 0; o >>= 1)
                    contrib += __shfl_down_sync(0xffffffffu, contrib, o);
                carry += __shfl_sync(0xffffffffu, contrib, 0);
                break;
            } else {
                int contrib = (jj >= 0) ? val : 0;
                #pragma unroll
                for (int o = 16; o > 0; o >>= 1)
                    contrib += __shfl_down_sync(0xffffffffu, contrib, o);
                carry += __shfl_sync(0xffffffffu, contrib, 0);
                j -= 32;
                if (j < 0) break;
            }
        }
        if (t == 0) {
            atomicExch(&desc[bid], (2ULL << 32) | (unsigned int)(carry + total));
            s_carry = carry;
        }
    }
    __syncthreads();
    int carry = s_carry;
    if (i < n) {
        int excl = carry + s[t] - v;
        row[i] = excl;
        cur[i] = excl;
        dinv[i] = rsqrtf((float)v + 1.0f);
        if (i == n - 1) row[n] = excl + v;
    }
}

// ---------------- slot scatter, 4 edges per thread ---------------------------
__global__ void slot_scatter_kernel(const int* __restrict__ src, const int* __restrict__ dst,
                                    int* __restrict__ cur, int* __restrict__ csr, int E) {
    int idx = blockIdx.x * blockDim.x + threadIdx.x;
    int EQ = E / 4;
    if (idx >= EQ) return;
    int4 s4 = reinterpret_cast<const int4*>(src)[idx];
    int4 d4 = reinterpret_cast<const int4*>(dst)[idx];
    int p0 = atomicAdd(&cur[d4.x], 1);
    int p1 = atomicAdd(&cur[d4.y], 1);
    int p2 = atomicAdd(&cur[d4.z], 1);
    int p3 = atomicAdd(&cur[d4.w], 1);
    csr[p0] = s4.x;
    csr[p1] = s4.y;
    csr[p2] = s4.z;
    csr[p3] = s4.w;
}

// ---------------- mma.sync fp16 helper ---------------------------------------
__device__ __forceinline__ void mma16816h(float c[4], const uint32_t a[4], const uint32_t b[2]) {
    asm volatile(
        "mma.sync.aligned.m16n8k16.row.col.f32.f16.f16.f32 "
        "{%0,%1,%2,%3}, {%4,%5,%6,%7}, {%8,%9}, {%0,%1,%2,%3};"
        : "+f"(c[0]), "+f"(c[1]), "+f"(c[2]), "+f"(c[3])
        : "r"(a[0]), "r"(a[1]), "r"(a[2]), "r"(a[3]), "r"(b[0]), "r"(b[1]));
}

// ---------------- fp16x2 HMMA GEMM: A single fp16, W fp16 hi/lo --------------
// BM=128, BK=64, LD=72. TRANS=false: A fp32 -> fp16. TRANS=true: A fp16,
// op(A)=relu(bias+dinv*A) -> fp16. C fp16 = dinv[r]*acc.
template<int BN, int KTOT, bool TRANS>
__global__ void __launch_bounds__(256, 2)
mma_gemm(const void* __restrict__ Av,
         const __half* __restrict__ Whi, const __half* __restrict__ Wlo,
         __half* __restrict__ C,
         const float* __restrict__ dinv, const float* __restrict__ bias, int M) {
    const int BM = 128, BK = 64, LD = 72;
    const int NW = BN / 2;
    const int NT = NW / 8;
    const int A_S  = 0;
    const int B_HI = A_S + BM * LD * 2;
    const int B_LO = B_HI + BN * LD * 2;

    extern __shared__ __align__(16) char smem[];
    __half* as   = reinterpret_cast<__half*>(smem + A_S);
    __half* bs_h = reinterpret_cast<__half*>(smem + B_HI);
    __half* bs_l = reinterpret_cast<__half*>(smem + B_LO);
    const uint32_t s_a  = smem_u32(as);
    const uint32_t s_bh = smem_u32(bs_h);
    const uint32_t s_bl = smem_u32(bs_l);

    const int tid  = threadIdx.x;
    const int wid  = tid >> 5;
    const int lane = tid & 31;
    const int g    = lane >> 2;
    const int t    = lane & 3;
    const int wm   = wid & 3;      // m-group: 32 rows (2 x 16 tiles)
    const int wn   = wid >> 2;     // n-group: NW cols
    const int row0 = blockIdx.x * BM;

    float acc[2][NT][4];
    #pragma unroll
    for (int mt = 0; mt < 2; mt++)
        #pragma unroll
        for (int nt = 0; nt < NT; nt++)
            #pragma unroll
            for (int q = 0; q < 4; q++) acc[mt][nt][q] = 0.0f;

    // LDSM lane offsets
    const uint32_t a_lrow = (uint32_t)(lane & 15);
    const uint32_t a_lk   = (uint32_t)((lane >> 4) << 3);
    const int b_msel = lane >> 3;
    const uint32_t b_lrow = (uint32_t)((b_msel & 2) ? 8 : 0) + (uint32_t)(lane & 7);
    const uint32_t b_lk   = (uint32_t)((b_msel & 1) << 3);

    for (int kc = 0; kc < KTOT; kc += BK) {
        // ---- A tile fill -> single fp16 ----
        #pragma unroll
        for (int it = 0; it < (BM * BK / 4) / 256; it++) {
            int idx = tid + it * 256;
            int row = idx >> 4;
            int k4  = (idx & 15) * 4;
            int gr  = row0 + row;
            float4 v = make_float4(0.f, 0.f, 0.f, 0.f);
            if (gr < M) {
                if constexpr (TRANS) {
                    const __half* Ah = reinterpret_cast<const __half*>(Av);
                    uint2 u = *reinterpret_cast<const uint2*>(Ah + (long long)gr * KTOT + kc + k4);
                    float2 f0 = __half22float2(*reinterpret_cast<__half2*>(&u.x));
                    float2 f1 = __half22float2(*reinterpret_cast<__half2*>(&u.y));
                    float di = dinv[gr];
                    float4 bb = *reinterpret_cast<const float4*>(bias + kc + k4);
                    v.x = fmaxf(fmaf(di, f0.x, bb.x), 0.f);
                    v.y = fmaxf(fmaf(di, f0.y, bb.y), 0.f);
                    v.z = fmaxf(fmaf(di, f1.x, bb.z), 0.f);
                    v.w = fmaxf(fmaf(di, f1.y, bb.w), 0.f);
                } else {
                    const float* Af = reinterpret_cast<const float*>(Av);
                    v = *reinterpret_cast<const float4*>(Af + (long long)gr * KTOT + kc + k4);
                }
            }
            __half2 h01 = __floats2half2_rn(v.x, v.y);
            __half2 h23 = __floats2half2_rn(v.z, v.w);
            *reinterpret_cast<uint2*>(as + row * LD + k4) =
                make_uint2(*reinterpret_cast<uint32_t*>(&h01), *reinterpret_cast<uint32_t*>(&h23));
        }
        // ---- B tiles fill (fp16 hi/lo) ----
        #pragma unroll
        for (int it = 0; it < (BN * BK / 4) / 256; it++) {
            int idx = tid + it * 256;
            int n  = idx >> 4;
            int k4 = (idx & 15) * 4;
            uint2 wh = *reinterpret_cast<const uint2*>(Whi + (long long)n * KTOT + kc + k4);
            uint2 wl = *reinterpret_cast<const uint2*>(Wlo + (long long)n * KTOT + kc + k4);
            int off = n * LD + k4;
            *reinterpret_cast<uint2*>(bs_h + off) = wh;
            *reinterpret_cast<uint2*>(bs_l + off) = wl;
        }
        __syncthreads();

        // ---- compute ----
        #pragma unroll
        for (int kk = 0; kk < BK; kk += 16) {
            uint32_t ah[2][4];
            #pragma unroll
            for (int mt = 0; mt < 2; mt++) {
                uint32_t ar = (uint32_t)(wm * 32 + mt * 16);
                uint32_t off = ((ar + a_lrow) * LD + (uint32_t)kk + a_lk) * 2;
                ldsm_x4(ah[mt], s_a + off);
            }
            #pragma unroll
            for (int p = 0; p < NT / 2; p++) {
                uint32_t bn = (uint32_t)(wn * NW + p * 16) + b_lrow;
                uint32_t boff = (bn * LD + (uint32_t)kk + b_lk) * 2;
                uint32_t bh[4], bl[4];
                ldsm_x4(bh, s_bh + boff);
                ldsm_x4(bl, s_bl + boff);
                #pragma unroll
                for (int q = 0; q < 2; q++) {
                    uint32_t bhq[2] = {bh[2 * q], bh[2 * q + 1]};
                    uint32_t blq[2] = {bl[2 * q], bl[2 * q + 1]};
                    #pragma unroll
                    for (int mt = 0; mt < 2; mt++) {
                        mma16816h(acc[mt][2 * p + q], ah[mt], bhq);
                        mma16816h(acc[mt][2 * p + q], ah[mt], blq);
                    }
                }
            }
        }
        __syncthreads();
    }

    // ---- epilogue: scale by dinv, store fp16 ----
    #pragma unroll
    for (int mt = 0; mt < 2; mt++) {
        int r0 = row0 + wm * 32 + mt * 16 + g;
        int r1 = r0 + 8;
        float s0 = (r0 < M) ? dinv[r0] : 0.0f;
        float s1 = (r1 < M) ? dinv[r1] : 0.0f;
        #pragma unroll
        for (int nt = 0; nt < NT; nt++) {
            int cc = wn * NW + nt * 8 + 2 * t;
            if (r0 < M)
                *reinterpret_cast<__half2*>(C + (long long)r0 * BN + cc) =
                    __floats2half2_rn(s0 * acc[mt][nt][0], s0 * acc[mt][nt][1]);
            if (r1 < M)
                *reinterpret_cast<__half2*>(C + (long long)r1 * BN + cc) =
                    __floats2half2_rn(s1 * acc[mt][nt][2], s1 * acc[mt][nt][3]);
        }
    }
}

// ---------------- pull layer 1 (fp16): agg1[d] = h2[d] + sum h2[src] ---------
__global__ void pull128_kernel(const __half* __restrict__ h2,
                               const int* __restrict__ row, const int* __restrict__ csr,
                               __half* __restrict__ agg, int n) {
    int gw = (blockIdx.x * blockDim.x + threadIdx.x) >> 5;
    int lane = threadIdx.x & 31;
    if (gw >= n) return;
    long long base = (long long)gw * HID_C + lane * 4;
    uint2 su = *reinterpret_cast<const uint2*>(h2 + base);
    float2 sf0 = __half22float2(*reinterpret_cast<__half2*>(&su.x));
    float2 sf1 = __half22float2(*reinterpret_cast<__half2*>(&su.y));
    float4 a = make_float4(sf0.x, sf0.y, sf1.x, sf1.y);
    int beg = row[gw], end = row[gw + 1];
    int j = beg;
    for (; j + 3 < end; j += 4) {
        int s0 = csr[j], s1 = csr[j + 1], s2 = csr[j + 2], s3 = csr[j + 3];
        uint2 u0 = *reinterpret_cast<const uint2*>(h2 + (long long)s0 * HID_C + lane * 4);
        uint2 u1 = *reinterpret_cast<const uint2*>(h2 + (long long)s1 * HID_C + lane * 4);
        uint2 u2 = *reinterpret_cast<const uint2*>(h2 + (long long)s2 * HID_C + lane * 4);
        uint2 u3 = *reinterpret_cast<const uint2*>(h2 + (long long)s3 * HID_C + lane * 4);
        float2 f;
        f = __half22float2(*reinterpret_cast<__half2*>(&u0.x)); a.x += f.x; a.y += f.y;
        f = __half22float2(*reinterpret_cast<__half2*>(&u0.y)); a.z += f.x; a.w += f.y;
        f = __half22float2(*reinterpret_cast<__half2*>(&u1.x)); a.x += f.x; a.y += f.y;
        f = __half22float2(*reinterpret_cast<__half2*>(&u1.y)); a.z += f.x; a.w += f.y;
        f = __half22float2(*reinterpret_cast<__half2*>(&u2.x)); a.x += f.x; a.y += f.y;
        f = __half22float2(*reinterpret_cast<__half2*>(&u2.y)); a.z += f.x; a.w += f.y;
        f = __half22float2(*reinterpret_cast<__half2*>(&u3.x)); a.x += f.x; a.y += f.y;
        f = __half22float2(*reinterpret_cast<__half2*>(&u3.y)); a.z += f.x; a.w += f.y;
    }
    for (; j < end; j++) {
        int s0 = csr[j];
        uint2 u0 = *reinterpret_cast<const uint2*>(h2 + (long long)s0 * HID_C + lane * 4);
        float2 f;
        f = __half22float2(*reinterpret_cast<__half2*>(&u0.x)); a.x += f.x; a.y += f.y;
        f = __half22float2(*reinterpret_cast<__half2*>(&u0.y)); a.z += f.x; a.w += f.y;
    }
    __half2 o0 = __floats2half2_rn(a.x, a.y);
    __half2 o1 = __floats2half2_rn(a.z, a.w);
    *reinterpret_cast<uint2*>(agg + base) =
        make_uint2(*reinterpret_cast<uint32_t*>(&o0), *reinterpret_cast<uint32_t*>(&o1));
}

// ---------------- pull layer 2 (fp16) + degi/desc reset tail -----------------
__global__ void pull64_kernel(const __half* __restrict__ z2,
                              const int* __restrict__ row, const int* __restrict__ csr,
                              const float* __restrict__ dinv, const float* __restrict__ b2,
                              float* __restrict__ out, int n,
                              int pull_blocks, int* __restrict__ degi,
                              unsigned long long* __restrict__ desc) {
    if ((int)blockIdx.x >= pull_blocks) {
        int base = ((int)blockIdx.x - pull_blocks) * 2048 + threadIdx.x * 8;
        #pragma unroll
        for (int k = 0; k < 8; k++) {
            int i = base + k;
            if (i < NN) degi[i] = 0;
            else if (i - NN < NB) desc[i - NN] = 0ULL;
        }
        return;
    }
    int gw = (blockIdx.x * blockDim.x + threadIdx.x) >> 5;
    int lane = threadIdx.x & 31;
    if (gw >= n) return;
    long long base = (long long)gw * OUT_C + lane * 2;
    float2 a = __half22float2(*reinterpret_cast<const __half2*>(z2 + base));
    int beg = row[gw], end = row[gw + 1];
    int j = beg;
    for (; j + 3 < end; j += 4) {
        int s0 = csr[j], s1 = csr[j + 1], s2 = csr[j + 2], s3 = csr[j + 3];
        float2 f0 = __half22float2(*reinterpret_cast<const __half2*>(z2 + (long long)s0 * OUT_C + lane * 2));
        float2 f1 = __half22float2(*reinterpret_cast<const __half2*>(z2 + (long long)s1 * OUT_C + lane * 2));
        float2 f2 = __half22float2(*reinterpret_cast<const __half2*>(z2 + (long long)s2 * OUT_C + lane * 2));
        float2 f3 = __half22float2(*reinterpret_cast<const __half2*>(z2 + (long long)s3 * OUT_C + lane * 2));
        a.x += (f0.x + f1.x) + (f2.x + f3.x);
        a.y += (f0.y + f1.y) + (f2.y + f3.y);
    }
    for (; j < end; j++) {
        int s0 = csr[j];
        float2 f0 = __half22float2(*reinterpret_cast<const __half2*>(z2 + (long long)s0 * OUT_C + lane * 2));
        a.x += f0.x; a.y += f0.y;
    }
    float di = dinv[gw];
    float2 bb = *reinterpret_cast<const float2*>(b2 + lane * 2);
    *reinterpret_cast<float2*>(out + base) =
        make_float2(fmaf(di, a.x, bb.x), fmaf(di, a.y, bb.y));
}

// ---------------- launch ----------------
extern "C" void kernel_launch(void* const* d_in, const int* in_sizes, int n_in,
                              void* d_out, int out_size) {
    const float* x  = (const float*)d_in[0];
    const int*   ei = (const int*)  d_in[1];
    const float* W1 = (const float*)d_in[2];
    const float* b1 = (const float*)d_in[3];
    const float* W2 = (const float*)d_in[4];
    const float* b2 = (const float*)d_in[5];
    float* out = (float*)d_out;

    const int E = in_sizes[1] / 2;
    const int* src = ei;
    const int* dst = ei + E;

    float *dinv;
    int *degi, *row, *cur, *csr;
    unsigned long long* desc;
    __half *h2, *agg1, *z2, *w1hi, *w1lo, *w2hi, *w2lo;
    cudaGetSymbolAddress((void**)&dinv, g_dinv);
    cudaGetSymbolAddress((void**)&degi, g_degi);
    cudaGetSymbolAddress((void**)&row,  g_row);
    cudaGetSymbolAddress((void**)&cur,  g_cur);
    cudaGetSymbolAddress((void**)&desc, g_desc);
    cudaGetSymbolAddress((void**)&csr,  g_csr);
    cudaGetSymbolAddress((void**)&h2,   g_h2);
    cudaGetSymbolAddress((void**)&agg1, g_agg1);
    cudaGetSymbolAddress((void**)&z2,   g_z2);
    cudaGetSymbolAddress((void**)&w1hi, g_w1hi);
    cudaGetSymbolAddress((void**)&w1lo, g_w1lo);
    cudaGetSymbolAddress((void**)&w2hi, g_w2hi);
    cudaGetSymbolAddress((void**)&w2lo, g_w2lo);

    const int LD = 72;
    const int SMEM1 = 128 * LD * 2 + 2 * 128 * LD * 2;   // 55296 B
    const int SMEM2 = 128 * LD * 2 + 2 * 64 * LD * 2;    // 36864 B
    cudaFuncSetAttribute(mma_gemm<HID_C, IN_C, false>,
                         cudaFuncAttributeMaxDynamicSharedMemorySize, SMEM1);
    cudaFuncSetAttribute(mma_gemm<OUT_C, HID_C, true>,
                         cudaFuncAttributeMaxDynamicSharedMemorySize, SMEM2);

    // 1) prep: vectorized degree histogram + W fp16 hi/lo conversion
    {
        int total = E / 4 + IN_C * HID_C + HID_C * OUT_C;
        prep_count_kernel<<<(total + 255) / 256, 256>>>(dst, E, W1, W2, degi,
                                                        w1hi, w1lo, w2hi, w2lo);
    }
    // 2) single-pass scan -> row/cur + dinv
    scan_kernel<<<NB, 256>>>(degi, desc, row, cur, dinv, NN);
    // 3) CSR slot scatter (4 edges/thread)
    slot_scatter_kernel<<<(E / 4 + 255) / 256, 256>>>(src, dst, cur, csr, E);

    // 4) GEMM1 (fp16x2 HMMA): h2 = fp16( dinv * (x @ W1) )
    mma_gemm<HID_C, IN_C, false><<<(NN + 127) / 128, 256, SMEM1>>>(
        x, w1hi, w1lo, h2, dinv, nullptr, NN);
    // 5) pull layer 1
    pull128_kernel<<<(NN * 32 + 255) / 256, 256>>>(h2, row, csr, agg1, NN);
    // 6) GEMM2: z2 = fp16( dinv * (relu(b1 + dinv*agg1) @ W2) )
    mma_gemm<OUT_C, HID_C, true><<<(NN + 127) / 128, 256, SMEM2>>>(
        agg1, w2hi, w2lo, z2, dinv, b1, NN);
    // 7) pull layer 2 + bias; tail blocks reset degi/desc
    {
        const int PULL_BLOCKS = (NN * 32 + 255) / 256;
        const int ZERO_BLOCKS = (NN + NB + 2047) / 2048;
        pull64_kernel<<<PULL_BLOCKS + ZERO_BLOCKS, 256>>>(
            z2, row, csr, dinv, b2, out, NN, PULL_BLOCKS, degi, desc);
    }
}

// round 14
// speedup vs baseline: 1.2464x; 1.0549x over previous
#include <cuda_runtime.h>
#include <cuda_bf16.h>
#include <cuda_fp16.h>
#include <cstdint>

#define NN     50000
#define IN_C   256
#define HID_C  128
#define OUT_C  64
#define E_MAX  800000
#define NB     ((NN + 255) / 256)   // 196 scan blocks

// ---------------- scratch ----------------
__device__ __align__(16) float g_dinv[NN];
__device__ __align__(16) int   g_degi[NN];          // zeroed at END of each call
__device__ __align__(16) int   g_row [NN + 1];
__device__ __align__(16) int   g_cur [NN];
__device__ __align__(16) unsigned long long g_desc[NB];  // zeroed at END of each call
__device__ __align__(16) int   g_csr [E_MAX];
__device__ __align__(16) __half g_h2  [NN * HID_C];
__device__ __align__(16) __half g_agg1[NN * HID_C];
__device__ __align__(16) __half g_z2  [NN * OUT_C];
__device__ __align__(16) __half g_w1h[HID_C * IN_C];   // fp16 weights, [N,K]
__device__ __align__(16) __half g_w2h[OUT_C * HID_C];

__device__ __forceinline__ uint32_t smem_u32(const void* p) {
    uint32_t a;
    asm("{ .reg .u64 t; cvta.to.shared.u64 t, %1; cvt.u32.u64 %0, t; }" : "=r"(a) : "l"(p));
    return a;
}
__device__ __forceinline__ void ldsm_x4(uint32_t (&r)[4], uint32_t saddr) {
    asm volatile("ldmatrix.sync.aligned.m8n8.x4.shared.b16 {%0,%1,%2,%3}, [%4];"
        : "=r"(r[0]), "=r"(r[1]), "=r"(r[2]), "=r"(r[3]) : "r"(saddr));
}

// ---------------- prep: deg histogram (x4 vectorized) + W fp16 ---------------
__global__ void prep_count_kernel(const int* __restrict__ dst, int E,
                                  const float* __restrict__ W1, const float* __restrict__ W2,
                                  int* __restrict__ degi,
                                  __half* __restrict__ w1h, __half* __restrict__ w2h) {
    const int EQ  = E / 4;                 // E divisible by 4 (800000)
    const int W1N = IN_C * HID_C;
    const int W2N = HID_C * OUT_C;
    int idx = blockIdx.x * blockDim.x + threadIdx.x;
    if (idx < EQ) {
        int4 d4 = reinterpret_cast<const int4*>(dst)[idx];
        atomicAdd(&degi[d4.x], 1);
        atomicAdd(&degi[d4.y], 1);
        atomicAdd(&degi[d4.z], 1);
        atomicAdd(&degi[d4.w], 1);
    } else if (idx < EQ + W1N) {
        int i = idx - EQ;
        int n = i / IN_C, k = i % IN_C;
        w1h[i] = __float2half_rn(W1[(long long)k * HID_C + n]);
    } else if (idx < EQ + W1N + W2N) {
        int i = idx - EQ - W1N;
        int n = i / HID_C, k = i % HID_C;
        w2h[i] = __float2half_rn(W2[(long long)k * OUT_C + n]);
    }
}

// ---------------- single-pass scan (decoupled lookback) + dinv ---------------
__global__ void scan_kernel(const int* __restrict__ deg, unsigned long long* __restrict__ desc,
                            int* __restrict__ row, int* __restrict__ cur,
                            float* __restrict__ dinv, int n) {
    __shared__ int s[256];
    __shared__ int s_carry;
    const int bid = blockIdx.x;
    const int t   = threadIdx.x;
    const int i   = bid * 256 + t;
    int v = (i < n) ? deg[i] : 0;
    s[t] = v;
    __syncthreads();
    #pragma unroll
    for (int off = 1; off < 256; off <<= 1) {
        int u = (t >= off) ? s[t - off] : 0;
        __syncthreads();
        s[t] += u;
        __syncthreads();
    }
    int total = s[255];
    if (t == 0) {
        unsigned long long d = ((unsigned long long)(bid == 0 ? 2u : 1u) << 32)
                             | (unsigned int)total;
        atomicExch(&desc[bid], d);
        if (bid == 0) s_carry = 0;
    }
    if (bid > 0 && t < 32) {
        int carry = 0;
        int j = bid - 1;
        while (true) {
            int jj = j - t;
            unsigned long long d = 0ULL;
            if (jj >= 0) d = *((volatile unsigned long long*)&desc[jj]);
            int st  = (int)(d >> 32);
            int val = (int)(d & 0xffffffffu);
            unsigned ready = __ballot_sync(0xffffffffu, (jj < 0) || st >= 1);
            if (ready != 0xffffffffu) continue;
            unsigned pmask = __ballot_sync(0xffffffffu, (jj >= 0) && st == 2);
            if (pmask) {
                int lp = __ffs(pmask) - 1;
                int contrib = (jj >= 0 && t <= lp) ? val : 0;
                #pragma unroll
                for (int o = 16; o > 0; o >>= 1)
                    contrib += __shfl_down_sync(0xffffffffu, contrib, o);
                carry += __shfl_sync(0xffffffffu, contrib, 0);
                break;
            } else {
                int contrib = (jj >= 0) ? val : 0;
                #pragma unroll
                for (int o = 16; o > 0; o >>= 1)
                    contrib += __shfl_down_sync(0xffffffffu, contrib, o);
                carry += __shfl_sync(0xffffffffu, contrib, 0);
                j -= 32;
                if (j < 0) break;
            }
        }
        if (t == 0) {
            atomicExch(&desc[bid], (2ULL << 32) | (unsigned int)(carry + total));
            s_carry = carry;
        }
    }
    __syncthreads();
    int carry = s_carry;
    if (i < n) {
        int excl = carry + s[t] - v;
        row[i] = excl;
        cur[i] = excl;
        dinv[i] = rsqrtf((float)v + 1.0f);
        if (i == n - 1) row[n] = excl + v;
    }
}

// ---------------- slot scatter, 4 edges per thread ---------------------------
__global__ void slot_scatter_kernel(const int* __restrict__ src, const int* __restrict__ dst,
                                    int* __restrict__ cur, int* __restrict__ csr, int E) {
    int idx = blockIdx.x * blockDim.x + threadIdx.x;
    int EQ = E / 4;
    if (idx >= EQ) return;
    int4 s4 = reinterpret_cast<const int4*>(src)[idx];
    int4 d4 = reinterpret_cast<const int4*>(dst)[idx];
    int p0 = atomicAdd(&cur[d4.x], 1);
    int p1 = atomicAdd(&cur[d4.y], 1);
    int p2 = atomicAdd(&cur[d4.z], 1);
    int p3 = atomicAdd(&cur[d4.w], 1);
    csr[p0] = s4.x;
    csr[p1] = s4.y;
    csr[p2] = s4.z;
    csr[p3] = s4.w;
}

// ---------------- mma.sync fp16 helper ---------------------------------------
__device__ __forceinline__ void mma16816h(float c[4], const uint32_t a[4], const uint32_t b[2]) {
    asm volatile(
        "mma.sync.aligned.m16n8k16.row.col.f32.f16.f16.f32 "
        "{%0,%1,%2,%3}, {%4,%5,%6,%7}, {%8,%9}, {%0,%1,%2,%3};"
        : "+f"(c[0]), "+f"(c[1]), "+f"(c[2]), "+f"(c[3])
        : "r"(a[0]), "r"(a[1]), "r"(a[2]), "r"(a[3]), "r"(b[0]), "r"(b[1]));
}

// ---------------- fp16x1 HMMA GEMM: A fp16, W fp16 ---------------------------
// BM=128, BK=64, LD=72. TRANS=false: A fp32 -> fp16. TRANS=true: A fp16,
// op(A)=relu(bias+dinv*A) -> fp16. C fp16 = dinv[r]*acc (fp32 accum).
template<int BN, int KTOT, bool TRANS>
__global__ void __launch_bounds__(256, 2)
mma_gemm(const void* __restrict__ Av,
         const __half* __restrict__ Wh,
         __half* __restrict__ C,
         const float* __restrict__ dinv, const float* __restrict__ bias, int M) {
    const int BM = 128, BK = 64, LD = 72;
    const int NW = BN / 2;
    const int NT = NW / 8;
    const int A_S = 0;
    const int B_S = A_S + BM * LD * 2;

    extern __shared__ __align__(16) char smem[];
    __half* as = reinterpret_cast<__half*>(smem + A_S);
    __half* bs = reinterpret_cast<__half*>(smem + B_S);
    const uint32_t s_a = smem_u32(as);
    const uint32_t s_b = smem_u32(bs);

    const int tid  = threadIdx.x;
    const int wid  = tid >> 5;
    const int lane = tid & 31;
    const int g    = lane >> 2;
    const int t    = lane & 3;
    const int wm   = wid & 3;      // m-group: 32 rows (2 x 16 tiles)
    const int wn   = wid >> 2;     // n-group: NW cols
    const int row0 = blockIdx.x * BM;

    float acc[2][NT][4];
    #pragma unroll
    for (int mt = 0; mt < 2; mt++)
        #pragma unroll
        for (int nt = 0; nt < NT; nt++)
            #pragma unroll
            for (int q = 0; q < 4; q++) acc[mt][nt][q] = 0.0f;

    // LDSM lane offsets
    const uint32_t a_lrow = (uint32_t)(lane & 15);
    const uint32_t a_lk   = (uint32_t)((lane >> 4) << 3);
    const int b_msel = lane >> 3;
    const uint32_t b_lrow = (uint32_t)((b_msel & 2) ? 8 : 0) + (uint32_t)(lane & 7);
    const uint32_t b_lk   = (uint32_t)((b_msel & 1) << 3);

    for (int kc = 0; kc < KTOT; kc += BK) {
        // ---- A tile fill -> fp16 ----
        #pragma unroll
        for (int it = 0; it < (BM * BK / 4) / 256; it++) {
            int idx = tid + it * 256;
            int row = idx >> 4;
            int k4  = (idx & 15) * 4;
            int gr  = row0 + row;
            float4 v = make_float4(0.f, 0.f, 0.f, 0.f);
            if (gr < M) {
                if constexpr (TRANS) {
                    const __half* Ah = reinterpret_cast<const __half*>(Av);
                    uint2 u = *reinterpret_cast<const uint2*>(Ah + (long long)gr * KTOT + kc + k4);
                    float2 f0 = __half22float2(*reinterpret_cast<__half2*>(&u.x));
                    float2 f1 = __half22float2(*reinterpret_cast<__half2*>(&u.y));
                    float di = dinv[gr];
                    float4 bb = *reinterpret_cast<const float4*>(bias + kc + k4);
                    v.x = fmaxf(fmaf(di, f0.x, bb.x), 0.f);
                    v.y = fmaxf(fmaf(di, f0.y, bb.y), 0.f);
                    v.z = fmaxf(fmaf(di, f1.x, bb.z), 0.f);
                    v.w = fmaxf(fmaf(di, f1.y, bb.w), 0.f);
                } else {
                    const float* Af = reinterpret_cast<const float*>(Av);
                    v = *reinterpret_cast<const float4*>(Af + (long long)gr * KTOT + kc + k4);
                }
            }
            __half2 h01 = __floats2half2_rn(v.x, v.y);
            __half2 h23 = __floats2half2_rn(v.z, v.w);
            *reinterpret_cast<uint2*>(as + row * LD + k4) =
                make_uint2(*reinterpret_cast<uint32_t*>(&h01), *reinterpret_cast<uint32_t*>(&h23));
        }
        // ---- B tile fill (fp16) ----
        #pragma unroll
        for (int it = 0; it < (BN * BK / 4) / 256; it++) {
            int idx = tid + it * 256;
            int n  = idx >> 4;
            int k4 = (idx & 15) * 4;
            uint2 wv = *reinterpret_cast<const uint2*>(Wh + (long long)n * KTOT + kc + k4);
            *reinterpret_cast<uint2*>(bs + n * LD + k4) = wv;
        }
        __syncthreads();

        // ---- compute ----
        #pragma unroll
        for (int kk = 0; kk < BK; kk += 16) {
            uint32_t ah[2][4];
            #pragma unroll
            for (int mt = 0; mt < 2; mt++) {
                uint32_t ar = (uint32_t)(wm * 32 + mt * 16);
                uint32_t off = ((ar + a_lrow) * LD + (uint32_t)kk + a_lk) * 2;
                ldsm_x4(ah[mt], s_a + off);
            }
            #pragma unroll
            for (int p = 0; p < NT / 2; p++) {
                uint32_t bn = (uint32_t)(wn * NW + p * 16) + b_lrow;
                uint32_t boff = (bn * LD + (uint32_t)kk + b_lk) * 2;
                uint32_t bv[4];
                ldsm_x4(bv, s_b + boff);
                #pragma unroll
                for (int q = 0; q < 2; q++) {
                    uint32_t bq[2] = {bv[2 * q], bv[2 * q + 1]};
                    #pragma unroll
                    for (int mt = 0; mt < 2; mt++)
                        mma16816h(acc[mt][2 * p + q], ah[mt], bq);
                }
            }
        }
        __syncthreads();
    }

    // ---- epilogue: scale by dinv, store fp16 ----
    #pragma unroll
    for (int mt = 0; mt < 2; mt++) {
        int r0 = row0 + wm * 32 + mt * 16 + g;
        int r1 = r0 + 8;
        float s0 = (r0 < M) ? dinv[r0] : 0.0f;
        float s1 = (r1 < M) ? dinv[r1] : 0.0f;
        #pragma unroll
        for (int nt = 0; nt < NT; nt++) {
            int cc = wn * NW + nt * 8 + 2 * t;
            if (r0 < M)
                *reinterpret_cast<__half2*>(C + (long long)r0 * BN + cc) =
                    __floats2half2_rn(s0 * acc[mt][nt][0], s0 * acc[mt][nt][1]);
            if (r1 < M)
                *reinterpret_cast<__half2*>(C + (long long)r1 * BN + cc) =
                    __floats2half2_rn(s1 * acc[mt][nt][2], s1 * acc[mt][nt][3]);
        }
    }
}

// ---------------- pull layer 1 (fp16): agg1[d] = h2[d] + sum h2[src] ---------
__global__ void pull128_kernel(const __half* __restrict__ h2,
                               const int* __restrict__ row, const int* __restrict__ csr,
                               __half* __restrict__ agg, int n) {
    int gw = (blockIdx.x * blockDim.x + threadIdx.x) >> 5;
    int lane = threadIdx.x & 31;
    if (gw >= n) return;
    long long base = (long long)gw * HID_C + lane * 4;
    uint2 su = *reinterpret_cast<const uint2*>(h2 + base);
    float2 sf0 = __half22float2(*reinterpret_cast<__half2*>(&su.x));
    float2 sf1 = __half22float2(*reinterpret_cast<__half2*>(&su.y));
    float4 a = make_float4(sf0.x, sf0.y, sf1.x, sf1.y);
    int beg = row[gw], end = row[gw + 1];
    int j = beg;
    for (; j + 3 < end; j += 4) {
        int s0 = csr[j], s1 = csr[j + 1], s2 = csr[j + 2], s3 = csr[j + 3];
        uint2 u0 = *reinterpret_cast<const uint2*>(h2 + (long long)s0 * HID_C + lane * 4);
        uint2 u1 = *reinterpret_cast<const uint2*>(h2 + (long long)s1 * HID_C + lane * 4);
        uint2 u2 = *reinterpret_cast<const uint2*>(h2 + (long long)s2 * HID_C + lane * 4);
        uint2 u3 = *reinterpret_cast<const uint2*>(h2 + (long long)s3 * HID_C + lane * 4);
        float2 f;
        f = __half22float2(*reinterpret_cast<__half2*>(&u0.x)); a.x += f.x; a.y += f.y;
        f = __half22float2(*reinterpret_cast<__half2*>(&u0.y)); a.z += f.x; a.w += f.y;
        f = __half22float2(*reinterpret_cast<__half2*>(&u1.x)); a.x += f.x; a.y += f.y;
        f = __half22float2(*reinterpret_cast<__half2*>(&u1.y)); a.z += f.x; a.w += f.y;
        f = __half22float2(*reinterpret_cast<__half2*>(&u2.x)); a.x += f.x; a.y += f.y;
        f = __half22float2(*reinterpret_cast<__half2*>(&u2.y)); a.z += f.x; a.w += f.y;
        f = __half22float2(*reinterpret_cast<__half2*>(&u3.x)); a.x += f.x; a.y += f.y;
        f = __half22float2(*reinterpret_cast<__half2*>(&u3.y)); a.z += f.x; a.w += f.y;
    }
    for (; j < end; j++) {
        int s0 = csr[j];
        uint2 u0 = *reinterpret_cast<const uint2*>(h2 + (long long)s0 * HID_C + lane * 4);
        float2 f;
        f = __half22float2(*reinterpret_cast<__half2*>(&u0.x)); a.x += f.x; a.y += f.y;
        f = __half22float2(*reinterpret_cast<__half2*>(&u0.y)); a.z += f.x; a.w += f.y;
    }
    __half2 o0 = __floats2half2_rn(a.x, a.y);
    __half2 o1 = __floats2half2_rn(a.z, a.w);
    *reinterpret_cast<uint2*>(agg + base) =
        make_uint2(*reinterpret_cast<uint32_t*>(&o0), *reinterpret_cast<uint32_t*>(&o1));
}

// ---------------- pull layer 2 (fp16) + degi/desc reset tail -----------------
__global__ void pull64_kernel(const __half* __restrict__ z2,
                              const int* __restrict__ row, const int* __restrict__ csr,
                              const float* __restrict__ dinv, const float* __restrict__ b2,
                              float* __restrict__ out, int n,
                              int pull_blocks, int* __restrict__ degi,
                              unsigned long long* __restrict__ desc) {
    if ((int)blockIdx.x >= pull_blocks) {
        int base = ((int)blockIdx.x - pull_blocks) * 2048 + threadIdx.x * 8;
        #pragma unroll
        for (int k = 0; k < 8; k++) {
            int i = base + k;
            if (i < NN) degi[i] = 0;
            else if (i - NN < NB) desc[i - NN] = 0ULL;
        }
        return;
    }
    int gw = (blockIdx.x * blockDim.x + threadIdx.x) >> 5;
    int lane = threadIdx.x & 31;
    if (gw >= n) return;
    long long base = (long long)gw * OUT_C + lane * 2;
    float2 a = __half22float2(*reinterpret_cast<const __half2*>(z2 + base));
    int beg = row[gw], end = row[gw + 1];
    int j = beg;
    for (; j + 3 < end; j += 4) {
        int s0 = csr[j], s1 = csr[j + 1], s2 = csr[j + 2], s3 = csr[j + 3];
        float2 f0 = __half22float2(*reinterpret_cast<const __half2*>(z2 + (long long)s0 * OUT_C + lane * 2));
        float2 f1 = __half22float2(*reinterpret_cast<const __half2*>(z2 + (long long)s1 * OUT_C + lane * 2));
        float2 f2 = __half22float2(*reinterpret_cast<const __half2*>(z2 + (long long)s2 * OUT_C + lane * 2));
        float2 f3 = __half22float2(*reinterpret_cast<const __half2*>(z2 + (long long)s3 * OUT_C + lane * 2));
        a.x += (f0.x + f1.x) + (f2.x + f3.x);
        a.y += (f0.y + f1.y) + (f2.y + f3.y);
    }
    for (; j < end; j++) {
        int s0 = csr[j];
        float2 f0 = __half22float2(*reinterpret_cast<const __half2*>(z2 + (long long)s0 * OUT_C + lane * 2));
        a.x += f0.x; a.y += f0.y;
    }
    float di = dinv[gw];
    float2 bb = *reinterpret_cast<const float2*>(b2 + lane * 2);
    *reinterpret_cast<float2*>(out + base) =
        make_float2(fmaf(di, a.x, bb.x), fmaf(di, a.y, bb.y));
}

// ---------------- launch ----------------
extern "C" void kernel_launch(void* const* d_in, const int* in_sizes, int n_in,
                              void* d_out, int out_size) {
    const float* x  = (const float*)d_in[0];
    const int*   ei = (const int*)  d_in[1];
    const float* W1 = (const float*)d_in[2];
    const float* b1 = (const float*)d_in[3];
    const float* W2 = (const float*)d_in[4];
    const float* b2 = (const float*)d_in[5];
    float* out = (float*)d_out;

    const int E = in_sizes[1] / 2;
    const int* src = ei;
    const int* dst = ei + E;

    float *dinv;
    int *degi, *row, *cur, *csr;
    unsigned long long* desc;
    __half *h2, *agg1, *z2, *w1h, *w2h;
    cudaGetSymbolAddress((void**)&dinv, g_dinv);
    cudaGetSymbolAddress((void**)&degi, g_degi);
    cudaGetSymbolAddress((void**)&row,  g_row);
    cudaGetSymbolAddress((void**)&cur,  g_cur);
    cudaGetSymbolAddress((void**)&desc, g_desc);
    cudaGetSymbolAddress((void**)&csr,  g_csr);
    cudaGetSymbolAddress((void**)&h2,   g_h2);
    cudaGetSymbolAddress((void**)&agg1, g_agg1);
    cudaGetSymbolAddress((void**)&z2,   g_z2);
    cudaGetSymbolAddress((void**)&w1h,  g_w1h);
    cudaGetSymbolAddress((void**)&w2h,  g_w2h);

    const int LD = 72;
    const int SMEM1 = 128 * LD * 2 + 128 * LD * 2;   // 36864 B
    const int SMEM2 = 128 * LD * 2 + 64 * LD * 2;    // 27648 B
    cudaFuncSetAttribute(mma_gemm<HID_C, IN_C, false>,
                         cudaFuncAttributeMaxDynamicSharedMemorySize, SMEM1);
    cudaFuncSetAttribute(mma_gemm<OUT_C, HID_C, true>,
                         cudaFuncAttributeMaxDynamicSharedMemorySize, SMEM2);

    // 1) prep: vectorized degree histogram + W fp16 conversion
    {
        int total = E / 4 + IN_C * HID_C + HID_C * OUT_C;
        prep_count_kernel<<<(total + 255) / 256, 256>>>(dst, E, W1, W2, degi, w1h, w2h);
    }
    // 2) single-pass scan -> row/cur + dinv
    scan_kernel<<<NB, 256>>>(degi, desc, row, cur, dinv, NN);
    // 3) CSR slot scatter (4 edges/thread)
    slot_scatter_kernel<<<(E / 4 + 255) / 256, 256>>>(src, dst, cur, csr, E);

    // 4) GEMM1 (fp16x1 HMMA): h2 = fp16( dinv * (x @ W1) )
    mma_gemm<HID_C, IN_C, false><<<(NN + 127) / 128, 256, SMEM1>>>(
        x, w1h, h2, dinv, nullptr, NN);
    // 5) pull layer 1
    pull128_kernel<<<(NN * 32 + 255) / 256, 256>>>(h2, row, csr, agg1, NN);
    // 6) GEMM2: z2 = fp16( dinv * (relu(b1 + dinv*agg1) @ W2) )
    mma_gemm<OUT_C, HID_C, true><<<(NN + 127) / 128, 256, SMEM2>>>(
        agg1, w2h, z2, dinv, b1, NN);
    // 7) pull layer 2 + bias; tail blocks reset degi/desc
    {
        const int PULL_BLOCKS = (NN * 32 + 255) / 256;
        const int ZERO_BLOCKS = (NN + NB + 2047) / 2048;
        pull64_kernel<<<PULL_BLOCKS + ZERO_BLOCKS, 256>>>(
            z2, row, csr, dinv, b2, out, NN, PULL_BLOCKS, degi, desc);
    }
}

// round 15
// speedup vs baseline: 1.2842x; 1.0303x over previous
#include <cuda_runtime.h>
#include <cuda_bf16.h>
#include <cuda_fp16.h>
#include <cstdint>

#define NN     50000
#define IN_C   256
#define HID_C  128
#define OUT_C  64
#define E_MAX  800000
#define NB     ((NN + 255) / 256)   // 196 scan blocks

// ---------------- scratch ----------------
__device__ __align__(16) float g_dinv[NN];
__device__ __align__(16) int   g_degi[NN];          // zeroed at END of each call
__device__ __align__(16) int   g_row [NN + 1];
__device__ __align__(16) int   g_cur [NN];
__device__ __align__(16) unsigned long long g_desc[NB];  // zeroed at END of each call
__device__ __align__(16) int   g_csr [E_MAX];
__device__ __align__(16) __half g_h2  [NN * HID_C];
__device__ __align__(16) __half g_agg1[NN * HID_C];
__device__ __align__(16) __half g_z2  [NN * OUT_C];
__device__ __align__(16) __half g_w1h[HID_C * IN_C];   // fp16 weights, [N,K]
__device__ __align__(16) __half g_w2h[OUT_C * HID_C];

__device__ __forceinline__ uint32_t smem_u32(const void* p) {
    uint32_t a;
    asm("{ .reg .u64 t; cvta.to.shared.u64 t, %1; cvt.u32.u64 %0, t; }" : "=r"(a) : "l"(p));
    return a;
}
__device__ __forceinline__ void ldsm_x4(uint32_t (&r)[4], uint32_t saddr) {
    asm volatile("ldmatrix.sync.aligned.m8n8.x4.shared.b16 {%0,%1,%2,%3}, [%4];"
        : "=r"(r[0]), "=r"(r[1]), "=r"(r[2]), "=r"(r[3]) : "r"(saddr));
}
__device__ __forceinline__ void cp16(uint32_t saddr, const void* g) {
    asm volatile("cp.async.cg.shared.global [%0], [%1], 16;" :: "r"(saddr), "l"(g));
}

// ---------------- prep: deg histogram (x4 vectorized) + W fp16 ---------------
__global__ void prep_count_kernel(const int* __restrict__ dst, int E,
                                  const float* __restrict__ W1, const float* __restrict__ W2,
                                  int* __restrict__ degi,
                                  __half* __restrict__ w1h, __half* __restrict__ w2h) {
    const int EQ  = E / 4;
    const int W1N = IN_C * HID_C;
    const int W2N = HID_C * OUT_C;
    int idx = blockIdx.x * blockDim.x + threadIdx.x;
    if (idx < EQ) {
        int4 d4 = reinterpret_cast<const int4*>(dst)[idx];
        atomicAdd(&degi[d4.x], 1);
        atomicAdd(&degi[d4.y], 1);
        atomicAdd(&degi[d4.z], 1);
        atomicAdd(&degi[d4.w], 1);
    } else if (idx < EQ + W1N) {
        int i = idx - EQ;
        int n = i / IN_C, k = i % IN_C;
        w1h[i] = __float2half_rn(W1[(long long)k * HID_C + n]);
    } else if (idx < EQ + W1N + W2N) {
        int i = idx - EQ - W1N;
        int n = i / HID_C, k = i % HID_C;
        w2h[i] = __float2half_rn(W2[(long long)k * OUT_C + n]);
    }
}

// ---------------- single-pass scan (decoupled lookback) + dinv ---------------
__global__ void scan_kernel(const int* __restrict__ deg, unsigned long long* __restrict__ desc,
                            int* __restrict__ row, int* __restrict__ cur,
                            float* __restrict__ dinv, int n) {
    __shared__ int s[256];
    __shared__ int s_carry;
    const int bid = blockIdx.x;
    const int t   = threadIdx.x;
    const int i   = bid * 256 + t;
    int v = (i < n) ? deg[i] : 0;
    s[t] = v;
    __syncthreads();
    #pragma unroll
    for (int off = 1; off < 256; off <<= 1) {
        int u = (t >= off) ? s[t - off] : 0;
        __syncthreads();
        s[t] += u;
        __syncthreads();
    }
    int total = s[255];
    if (t == 0) {
        unsigned long long d = ((unsigned long long)(bid == 0 ? 2u : 1u) << 32)
                             | (unsigned int)total;
        atomicExch(&desc[bid], d);
        if (bid == 0) s_carry = 0;
    }
    if (bid > 0 && t < 32) {
        int carry = 0;
        int j = bid - 1;
        while (true) {
            int jj = j - t;
            unsigned long long d = 0ULL;
            if (jj >= 0) d = *((volatile unsigned long long*)&desc[jj]);
            int st  = (int)(d >> 32);
            int val = (int)(d & 0xffffffffu);
            unsigned ready = __ballot_sync(0xffffffffu, (jj < 0) || st >= 1);
            if (ready != 0xffffffffu) continue;
            unsigned pmask = __ballot_sync(0xffffffffu, (jj >= 0) && st == 2);
            if (pmask) {
                int lp = __ffs(pmask) - 1;
                int contrib = (jj >= 0 && t <= lp) ? val : 0;
                #pragma unroll
                for (int o = 16; o > 0; o >>= 1)
                    contrib += __shfl_down_sync(0xffffffffu, contrib, o);
                carry += __shfl_sync(0xffffffffu, contrib, 0);
                break;
            } else {
                int contrib = (jj >= 0) ? val : 0;
                #pragma unroll
                for (int o = 16; o > 0; o >>= 1)
                    contrib += __shfl_down_sync(0xffffffffu, contrib, o);
                carry += __shfl_sync(0xffffffffu, contrib, 0);
                j -= 32;
                if (j < 0) break;
            }
        }
        if (t == 0) {
            atomicExch(&desc[bid], (2ULL << 32) | (unsigned int)(carry + total));
            s_carry = carry;
        }
    }
    __syncthreads();
    int carry = s_carry;
    if (i < n) {
        int excl = carry + s[t] - v;
        row[i] = excl;
        cur[i] = excl;
        dinv[i] = rsqrtf((float)v + 1.0f);
        if (i == n - 1) row[n] = excl + v;
    }
}

// ---------------- slot scatter, 4 edges per thread ---------------------------
__global__ void slot_scatter_kernel(const int* __restrict__ src, const int* __restrict__ dst,
                                    int* __restrict__ cur, int* __restrict__ csr, int E) {
    int idx = blockIdx.x * blockDim.x + threadIdx.x;
    int EQ = E / 4;
    if (idx >= EQ) return;
    int4 s4 = reinterpret_cast<const int4*>(src)[idx];
    int4 d4 = reinterpret_cast<const int4*>(dst)[idx];
    int p0 = atomicAdd(&cur[d4.x], 1);
    int p1 = atomicAdd(&cur[d4.y], 1);
    int p2 = atomicAdd(&cur[d4.z], 1);
    int p3 = atomicAdd(&cur[d4.w], 1);
    csr[p0] = s4.x;
    csr[p1] = s4.y;
    csr[p2] = s4.z;
    csr[p3] = s4.w;
}

// ---------------- mma.sync fp16 helper ---------------------------------------
__device__ __forceinline__ void mma16816h(float c[4], const uint32_t a[4], const uint32_t b[2]) {
    asm volatile(
        "mma.sync.aligned.m16n8k16.row.col.f32.f16.f16.f32 "
        "{%0,%1,%2,%3}, {%4,%5,%6,%7}, {%8,%9}, {%0,%1,%2,%3};"
        : "+f"(c[0]), "+f"(c[1]), "+f"(c[2]), "+f"(c[3])
        : "r"(a[0]), "r"(a[1]), "r"(a[2]), "r"(a[3]), "r"(b[0]), "r"(b[1]));
}

// ---------------- fp16x1 HMMA GEMM, software-pipelined -----------------------
// BM=128, BK=32, LD=40 (conflict-free), double-buffered smem stages.
// A: register-prefetched LDG (+fp16 convert at STS). B: cp.async.
// TRANS=false: A fp32. TRANS=true: A fp16, op(A)=relu(bias+dinv*A).
// C fp16 = dinv[r]*acc (fp32 accum).
template<int BN, int KTOT, bool TRANS>
__global__ void __launch_bounds__(256, 2)
mma_gemm(const void* __restrict__ Av,
         const __half* __restrict__ Wh,
         __half* __restrict__ C,
         const float* __restrict__ dinv, const float* __restrict__ bias, int M) {
    const int BM = 128, BK = 32, LD = 40;
    const int NCH = KTOT / BK;
    const int NW  = BN / 2;
    const int NT  = NW / 8;
    const int ASZ = BM * LD * 2;           // bytes per A stage
    const int BSZ = BN * LD * 2;           // bytes per B stage
    const int STG = ASZ + BSZ;
    const int BCH = (BN * BK * 2) / 16 / 256;  // cp.async 16B chunks per thread (1 or 2)

    extern __shared__ __align__(16) char smem[];
    const uint32_t s0 = smem_u32(smem);

    const int tid  = threadIdx.x;
    const int wid  = tid >> 5;
    const int lane = tid & 31;
    const int g    = lane >> 2;
    const int t    = lane & 3;
    const int wm   = wid & 3;
    const int wn   = wid >> 2;
    const int row0 = blockIdx.x * BM;

    float acc[2][NT][4];
    #pragma unroll
    for (int mt = 0; mt < 2; mt++)
        #pragma unroll
        for (int nt = 0; nt < NT; nt++)
            #pragma unroll
            for (int q = 0; q < 4; q++) acc[mt][nt][q] = 0.0f;

    // LDSM lane offsets
    const uint32_t a_lrow = (uint32_t)(lane & 15);
    const uint32_t a_lk   = (uint32_t)((lane >> 4) << 3);
    const int b_msel = lane >> 3;
    const uint32_t b_lrow = (uint32_t)((b_msel & 2) ? 8 : 0) + (uint32_t)(lane & 7);
    const uint32_t b_lk   = (uint32_t)((b_msel & 1) << 3);

    // per-thread A-fill mapping: 4 quads, row = idx>>3, k4 = (idx&7)*4
    int a_row[4], a_k4[4];
    #pragma unroll
    for (int it = 0; it < 4; it++) {
        int idx = tid + it * 256;
        a_row[it] = idx >> 3;
        a_k4[it]  = (idx & 7) * 4;
    }

    // A prefetch registers
    float4 aregf[4];   // TRANS=false path
    uint2  aregh[4];   // TRANS=true path

    auto prefetch_A = [&](int kc) {
        #pragma unroll
        for (int it = 0; it < 4; it++) {
            int gr = row0 + a_row[it];
            if constexpr (TRANS) {
                aregh[it] = make_uint2(0u, 0u);
                if (gr < M)
                    aregh[it] = *reinterpret_cast<const uint2*>(
                        reinterpret_cast<const __half*>(Av) + (long long)gr * KTOT + kc + a_k4[it]);
            } else {
                aregf[it] = make_float4(0.f, 0.f, 0.f, 0.f);
                if (gr < M)
                    aregf[it] = *reinterpret_cast<const float4*>(
                        reinterpret_cast<const float*>(Av) + (long long)gr * KTOT + kc + a_k4[it]);
            }
        }
    };
    auto cpasync_B = [&](int kc, int st) {
        uint32_t bb = s0 + st * STG + ASZ;
        #pragma unroll
        for (int i = 0; i < BCH; i++) {
            int cid = tid + i * 256;
            int n   = cid >> 2;
            int k8  = (cid & 3) * 8;
            cp16(bb + (n * LD + k8) * 2, Wh + (long long)n * KTOT + kc + k8);
        }
        asm volatile("cp.async.commit_group;");
    };
    auto sts_A = [&](int kc, int st) {
        __half* as = reinterpret_cast<__half*>(smem + st * STG);
        #pragma unroll
        for (int it = 0; it < 4; it++) {
            float4 v;
            if constexpr (TRANS) {
                int gr = row0 + a_row[it];
                float2 f0 = __half22float2(*reinterpret_cast<__half2*>(&aregh[it].x));
                float2 f1 = __half22float2(*reinterpret_cast<__half2*>(&aregh[it].y));
                float di = (gr < M) ? dinv[gr] : 0.0f;
                float4 bb = *reinterpret_cast<const float4*>(bias + kc + a_k4[it]);
                v.x = fmaxf(fmaf(di, f0.x, bb.x), 0.f);
                v.y = fmaxf(fmaf(di, f0.y, bb.y), 0.f);
                v.z = fmaxf(fmaf(di, f1.x, bb.z), 0.f);
                v.w = fmaxf(fmaf(di, f1.y, bb.w), 0.f);
                if (gr >= M) v = make_float4(0.f, 0.f, 0.f, 0.f);
            } else {
                v = aregf[it];
            }
            __half2 h01 = __floats2half2_rn(v.x, v.y);
            __half2 h23 = __floats2half2_rn(v.z, v.w);
            *reinterpret_cast<uint2*>(as + a_row[it] * LD + a_k4[it]) =
                make_uint2(*reinterpret_cast<uint32_t*>(&h01), *reinterpret_cast<uint32_t*>(&h23));
        }
    };

    // ---- prologue ----
    prefetch_A(0);
    cpasync_B(0, 0);

    for (int c = 0; c < NCH; c++) {
        const int s = c & 1;
        sts_A(c * BK, s);
        asm volatile("cp.async.wait_group 0;");
        __syncthreads();
        if (c + 1 < NCH) {
            prefetch_A((c + 1) * BK);
            cpasync_B((c + 1) * BK, 1 - s);
        }

        const uint32_t s_a = s0 + s * STG;
        const uint32_t s_b = s_a + ASZ;
        #pragma unroll
        for (int kk = 0; kk < BK; kk += 16) {
            uint32_t ah[2][4];
            #pragma unroll
            for (int mt = 0; mt < 2; mt++) {
                uint32_t ar = (uint32_t)(wm * 32 + mt * 16);
                uint32_t off = ((ar + a_lrow) * LD + (uint32_t)kk + a_lk) * 2;
                ldsm_x4(ah[mt], s_a + off);
            }
            #pragma unroll
            for (int p = 0; p < NT / 2; p++) {
                uint32_t bn = (uint32_t)(wn * NW + p * 16) + b_lrow;
                uint32_t boff = (bn * LD + (uint32_t)kk + b_lk) * 2;
                uint32_t bv[4];
                ldsm_x4(bv, s_b + boff);
                #pragma unroll
                for (int q = 0; q < 2; q++) {
                    uint32_t bq[2] = {bv[2 * q], bv[2 * q + 1]};
                    #pragma unroll
                    for (int mt = 0; mt < 2; mt++)
                        mma16816h(acc[mt][2 * p + q], ah[mt], bq);
                }
            }
        }
    }

    __syncthreads();   // all compute done before epilogue overwrites nothing; cheap
    // ---- epilogue: scale by dinv, store fp16 ----
    #pragma unroll
    for (int mt = 0; mt < 2; mt++) {
        int r0 = row0 + wm * 32 + mt * 16 + g;
        int r1 = r0 + 8;
        float s0f = (r0 < M) ? dinv[r0] : 0.0f;
        float s1f = (r1 < M) ? dinv[r1] : 0.0f;
        #pragma unroll
        for (int nt = 0; nt < NT; nt++) {
            int cc = wn * NW + nt * 8 + 2 * t;
            if (r0 < M)
                *reinterpret_cast<__half2*>(C + (long long)r0 * BN + cc) =
                    __floats2half2_rn(s0f * acc[mt][nt][0], s0f * acc[mt][nt][1]);
            if (r1 < M)
                *reinterpret_cast<__half2*>(C + (long long)r1 * BN + cc) =
                    __floats2half2_rn(s1f * acc[mt][nt][2], s1f * acc[mt][nt][3]);
        }
    }
}

// ---------------- pull layer 1 (fp16): agg1[d] = h2[d] + sum h2[src] ---------
__global__ void pull128_kernel(const __half* __restrict__ h2,
                               const int* __restrict__ row, const int* __restrict__ csr,
                               __half* __restrict__ agg, int n) {
    int gw = (blockIdx.x * blockDim.x + threadIdx.x) >> 5;
    int lane = threadIdx.x & 31;
    if (gw >= n) return;
    long long base = (long long)gw * HID_C + lane * 4;
    uint2 su = *reinterpret_cast<const uint2*>(h2 + base);
    float2 sf0 = __half22float2(*reinterpret_cast<__half2*>(&su.x));
    float2 sf1 = __half22float2(*reinterpret_cast<__half2*>(&su.y));
    float4 a = make_float4(sf0.x, sf0.y, sf1.x, sf1.y);
    int beg = row[gw], end = row[gw + 1];
    int j = beg;
    for (; j + 3 < end; j += 4) {
        int s0 = csr[j], s1 = csr[j + 1], s2 = csr[j + 2], s3 = csr[j + 3];
        uint2 u0 = *reinterpret_cast<const uint2*>(h2 + (long long)s0 * HID_C + lane * 4);
        uint2 u1 = *reinterpret_cast<const uint2*>(h2 + (long long)s1 * HID_C + lane * 4);
        uint2 u2 = *reinterpret_cast<const uint2*>(h2 + (long long)s2 * HID_C + lane * 4);
        uint2 u3 = *reinterpret_cast<const uint2*>(h2 + (long long)s3 * HID_C + lane * 4);
        float2 f;
        f = __half22float2(*reinterpret_cast<__half2*>(&u0.x)); a.x += f.x; a.y += f.y;
        f = __half22float2(*reinterpret_cast<__half2*>(&u0.y)); a.z += f.x; a.w += f.y;
        f = __half22float2(*reinterpret_cast<__half2*>(&u1.x)); a.x += f.x; a.y += f.y;
        f = __half22float2(*reinterpret_cast<__half2*>(&u1.y)); a.z += f.x; a.w += f.y;
        f = __half22float2(*reinterpret_cast<__half2*>(&u2.x)); a.x += f.x; a.y += f.y;
        f = __half22float2(*reinterpret_cast<__half2*>(&u2.y)); a.z += f.x; a.w += f.y;
        f = __half22float2(*reinterpret_cast<__half2*>(&u3.x)); a.x += f.x; a.y += f.y;
        f = __half22float2(*reinterpret_cast<__half2*>(&u3.y)); a.z += f.x; a.w += f.y;
    }
    for (; j < end; j++) {
        int s0 = csr[j];
        uint2 u0 = *reinterpret_cast<const uint2*>(h2 + (long long)s0 * HID_C + lane * 4);
        float2 f;
        f = __half22float2(*reinterpret_cast<__half2*>(&u0.x)); a.x += f.x; a.y += f.y;
        f = __half22float2(*reinterpret_cast<__half2*>(&u0.y)); a.z += f.x; a.w += f.y;
    }
    __half2 o0 = __floats2half2_rn(a.x, a.y);
    __half2 o1 = __floats2half2_rn(a.z, a.w);
    *reinterpret_cast<uint2*>(agg + base) =
        make_uint2(*reinterpret_cast<uint32_t*>(&o0), *reinterpret_cast<uint32_t*>(&o1));
}

// ---------------- pull layer 2 (fp16) + degi/desc reset tail -----------------
__global__ void pull64_kernel(const __half* __restrict__ z2,
                              const int* __restrict__ row, const int* __restrict__ csr,
                              const float* __restrict__ dinv, const float* __restrict__ b2,
                              float* __restrict__ out, int n,
                              int pull_blocks, int* __restrict__ degi,
                              unsigned long long* __restrict__ desc) {
    if ((int)blockIdx.x >= pull_blocks) {
        int base = ((int)blockIdx.x - pull_blocks) * 2048 + threadIdx.x * 8;
        #pragma unroll
        for (int k = 0; k < 8; k++) {
            int i = base + k;
            if (i < NN) degi[i] = 0;
            else if (i - NN < NB) desc[i - NN] = 0ULL;
        }
        return;
    }
    int gw = (blockIdx.x * blockDim.x + threadIdx.x) >> 5;
    int lane = threadIdx.x & 31;
    if (gw >= n) return;
    long long base = (long long)gw * OUT_C + lane * 2;
    float2 a = __half22float2(*reinterpret_cast<const __half2*>(z2 + base));
    int beg = row[gw], end = row[gw + 1];
    int j = beg;
    for (; j + 3 < end; j += 4) {
        int s0 = csr[j], s1 = csr[j + 1], s2 = csr[j + 2], s3 = csr[j + 3];
        float2 f0 = __half22float2(*reinterpret_cast<const __half2*>(z2 + (long long)s0 * OUT_C + lane * 2));
        float2 f1 = __half22float2(*reinterpret_cast<const __half2*>(z2 + (long long)s1 * OUT_C + lane * 2));
        float2 f2 = __half22float2(*reinterpret_cast<const __half2*>(z2 + (long long)s2 * OUT_C + lane * 2));
        float2 f3 = __half22float2(*reinterpret_cast<const __half2*>(z2 + (long long)s3 * OUT_C + lane * 2));
        a.x += (f0.x + f1.x) + (f2.x + f3.x);
        a.y += (f0.y + f1.y) + (f2.y + f3.y);
    }
    for (; j < end; j++) {
        int s0 = csr[j];
        float2 f0 = __half22float2(*reinterpret_cast<const __half2*>(z2 + (long long)s0 * OUT_C + lane * 2));
        a.x += f0.x; a.y += f0.y;
    }
    float di = dinv[gw];
    float2 bb = *reinterpret_cast<const float2*>(b2 + lane * 2);
    *reinterpret_cast<float2*>(out + base) =
        make_float2(fmaf(di, a.x, bb.x), fmaf(di, a.y, bb.y));
}

// ---------------- launch ----------------
extern "C" void kernel_launch(void* const* d_in, const int* in_sizes, int n_in,
                              void* d_out, int out_size) {
    const float* x  = (const float*)d_in[0];
    const int*   ei = (const int*)  d_in[1];
    const float* W1 = (const float*)d_in[2];
    const float* b1 = (const float*)d_in[3];
    const float* W2 = (const float*)d_in[4];
    const float* b2 = (const float*)d_in[5];
    float* out = (float*)d_out;

    const int E = in_sizes[1] / 2;
    const int* src = ei;
    const int* dst = ei + E;

    float *dinv;
    int *degi, *row, *cur, *csr;
    unsigned long long* desc;
    __half *h2, *agg1, *z2, *w1h, *w2h;
    cudaGetSymbolAddress((void**)&dinv, g_dinv);
    cudaGetSymbolAddress((void**)&degi, g_degi);
    cudaGetSymbolAddress((void**)&row,  g_row);
    cudaGetSymbolAddress((void**)&cur,  g_cur);
    cudaGetSymbolAddress((void**)&desc, g_desc);
    cudaGetSymbolAddress((void**)&csr,  g_csr);
    cudaGetSymbolAddress((void**)&h2,   g_h2);
    cudaGetSymbolAddress((void**)&agg1, g_agg1);
    cudaGetSymbolAddress((void**)&z2,   g_z2);
    cudaGetSymbolAddress((void**)&w1h,  g_w1h);
    cudaGetSymbolAddress((void**)&w2h,  g_w2h);

    const int LD = 40;
    const int SMEM1 = 2 * (128 * LD * 2 + 128 * LD * 2);   // 40960 B
    const int SMEM2 = 2 * (128 * LD * 2 + 64 * LD * 2);    // 30720 B
    cudaFuncSetAttribute(mma_gemm<HID_C, IN_C, false>,
                         cudaFuncAttributeMaxDynamicSharedMemorySize, SMEM1);
    cudaFuncSetAttribute(mma_gemm<OUT_C, HID_C, true>,
                         cudaFuncAttributeMaxDynamicSharedMemorySize, SMEM2);

    // 1) prep: vectorized degree histogram + W fp16 conversion
    {
        int total = E / 4 + IN_C * HID_C + HID_C * OUT_C;
        prep_count_kernel<<<(total + 255) / 256, 256>>>(dst, E, W1, W2, degi, w1h, w2h);
    }
    // 2) single-pass scan -> row/cur + dinv
    scan_kernel<<<NB, 256>>>(degi, desc, row, cur, dinv, NN);
    // 3) CSR slot scatter (4 edges/thread)
    slot_scatter_kernel<<<(E / 4 + 255) / 256, 256>>>(src, dst, cur, csr, E);

    // 4) GEMM1 (pipelined fp16x1 HMMA): h2 = fp16( dinv * (x @ W1) )
    mma_gemm<HID_C, IN_C, false><<<(NN + 127) / 128, 256, SMEM1>>>(
        x, w1h, h2, dinv, nullptr, NN);
    // 5) pull layer 1
    pull128_kernel<<<(NN * 32 + 255) / 256, 256>>>(h2, row, csr, agg1, NN);
    // 6) GEMM2: z2 = fp16( dinv * (relu(b1 + dinv*agg1) @ W2) )
    mma_gemm<OUT_C, HID_C, true><<<(NN + 127) / 128, 256, SMEM2>>>(
        agg1, w2h, z2, dinv, b1, NN);
    // 7) pull layer 2 + bias; tail blocks reset degi/desc
    {
        const int PULL_BLOCKS = (NN * 32 + 255) / 256;
        const int ZERO_BLOCKS = (NN + NB + 2047) / 2048;
        pull64_kernel<<<PULL_BLOCKS + ZERO_BLOCKS, 256>>>(
            z2, row, csr, dinv, b2, out, NN, PULL_BLOCKS, degi, desc);
    }
}